// round 1
// baseline (speedup 1.0000x reference)
#include <cuda_runtime.h>
#include <math.h>

#define N_BANDS 15
#define BW_     129
#define HOP_    64
#define NFREQ   1025
#define EMB     128
#define MLPD    512
#define OUTC    516      // BW*C*REIM
#define TLEN    2048
#define TM      64
#define NW      8
#define NTHREADS 256
#define SMEM_BYTES ((TM*EMB + TM*MLPD)*4)   // 32KB qn + 128KB h = 160KB

__global__ void omem_zero_kernel(float4* __restrict__ out, int n4) {
    int i = blockIdx.x*blockDim.x + threadIdx.x;
    int stride = gridDim.x*blockDim.x;
    float4 z = make_float4(0.f,0.f,0.f,0.f);
    for (; i < n4; i += stride) out[i] = z;
}

__global__ __launch_bounds__(NTHREADS, 1)
void omem_band_mlp_kernel(const float* __restrict__ q,
                          const float* __restrict__ ln_gamma,
                          const float* __restrict__ ln_beta,
                          const float* __restrict__ W1,
                          const float* __restrict__ b1,
                          const float* __restrict__ W2,
                          const float* __restrict__ b2,
                          const float* __restrict__ fw,
                          float* __restrict__ out) {
    extern __shared__ float sm[];
    float* qn_s = sm;               // [TM][EMB]
    float* h_s  = sm + TM*EMB;      // [TM][MLPD]

    const int b  = blockIdx.z;
    const int n  = blockIdx.y;
    const int t0 = blockIdx.x * TM;
    const int warp = threadIdx.x >> 5;
    const int lane = threadIdx.x & 31;
    const int row0 = warp * 8;

    // ---------------- LayerNorm (warp-per-token) ----------------
    const float* qb = q + ((size_t)(b*N_BANDS + n)*TLEN + t0)*EMB;
    float4 gg = ((const float4*)(ln_gamma + (size_t)n*EMB))[lane];
    float4 bet = ((const float4*)(ln_beta  + (size_t)n*EMB))[lane];
    for (int i = warp; i < TM; i += NW) {
        float4 v = ((const float4*)(qb + (size_t)i*EMB))[lane];
        float s  = v.x + v.y + v.z + v.w;
        float s2 = v.x*v.x + v.y*v.y + v.z*v.z + v.w*v.w;
        #pragma unroll
        for (int off = 16; off; off >>= 1) {
            s  += __shfl_xor_sync(0xffffffffu, s,  off);
            s2 += __shfl_xor_sync(0xffffffffu, s2, off);
        }
        float mu  = s  * (1.0f/EMB);
        float var = s2 * (1.0f/EMB) - mu*mu;
        float rs  = rsqrtf(var + 1e-5f);
        float4 o;
        o.x = (v.x - mu)*rs*gg.x + bet.x;
        o.y = (v.y - mu)*rs*gg.y + bet.y;
        o.z = (v.z - mu)*rs*gg.z + bet.z;
        o.w = (v.w - mu)*rs*gg.w + bet.w;
        ((float4*)(qn_s + i*EMB))[lane] = o;
    }
    __syncthreads();

    // ---------------- GEMM1: h = tanh(qn @ W1 + b1) ----------------
    const float* W1n = W1 + (size_t)n*EMB*MLPD;
    const float* b1n = b1 + (size_t)n*MLPD;
    for (int c0 = 0; c0 < MLPD; c0 += 128) {
        const int col = c0 + lane*4;
        float acc[8][4];
        #pragma unroll
        for (int r = 0; r < 8; r++) { acc[r][0]=0.f; acc[r][1]=0.f; acc[r][2]=0.f; acc[r][3]=0.f; }
        #pragma unroll 2
        for (int k = 0; k < EMB; k++) {
            float4 w = *(const float4*)(W1n + (size_t)k*MLPD + col);
            #pragma unroll
            for (int r = 0; r < 8; r++) {
                float hv = qn_s[(row0+r)*EMB + k];   // warp-broadcast LDS
                acc[r][0] += hv*w.x; acc[r][1] += hv*w.y;
                acc[r][2] += hv*w.z; acc[r][3] += hv*w.w;
            }
        }
        float4 bias = *(const float4*)(b1n + col);
        #pragma unroll
        for (int r = 0; r < 8; r++) {
            float4 o;
            o.x = tanhf(acc[r][0] + bias.x);
            o.y = tanhf(acc[r][1] + bias.y);
            o.z = tanhf(acc[r][2] + bias.z);
            o.w = tanhf(acc[r][3] + bias.w);
            *(float4*)(h_s + (row0+r)*MLPD + col) = o;
        }
    }
    __syncthreads();

    // ---------------- GEMM2 (paired a/g cols) + gate + scatter ----------------
    const float* W2n = W2 + (size_t)n*MLPD*(2*OUTC);
    const float* b2n = b2 + (size_t)n*(2*OUTC);
    const float* fwn = fw + (size_t)n*BW_;

    for (int c0 = 0; c0 < 512; c0 += 128) {
        const int col = c0 + lane*4;
        float aa[8][4], ag[8][4];
        #pragma unroll
        for (int r = 0; r < 8; r++) {
            aa[r][0]=0.f; aa[r][1]=0.f; aa[r][2]=0.f; aa[r][3]=0.f;
            ag[r][0]=0.f; ag[r][1]=0.f; ag[r][2]=0.f; ag[r][3]=0.f;
        }
        #pragma unroll 2
        for (int k = 0; k < MLPD; k++) {
            const float* wrow = W2n + (size_t)k*(2*OUTC);
            float4 wa = *(const float4*)(wrow + col);
            float4 wg = *(const float4*)(wrow + OUTC + col);
            #pragma unroll
            for (int r = 0; r < 8; r++) {
                float hv = h_s[(row0+r)*MLPD + k];   // warp-broadcast LDS
                aa[r][0] += hv*wa.x; aa[r][1] += hv*wa.y;
                aa[r][2] += hv*wa.z; aa[r][3] += hv*wa.w;
                ag[r][0] += hv*wg.x; ag[r][1] += hv*wg.y;
                ag[r][2] += hv*wg.z; ag[r][3] += hv*wg.w;
            }
        }
        float4 ba4 = *(const float4*)(b2n + col);
        float4 bg4 = *(const float4*)(b2n + OUTC + col);
        float ba_[4] = {ba4.x, ba4.y, ba4.z, ba4.w};
        float bg_[4] = {bg4.x, bg4.y, bg4.z, bg4.w};
        #pragma unroll
        for (int j = 0; j < 4; j++) {
            int cj  = col + j;
            int c   = (cj >= 258) ? 1 : 0;
            int rem = cj - c*258;
            int f   = rem >> 1;
            int ri  = rem & 1;
            float fwv = fwn[f];
            size_t obase = (((size_t)(b*2 + c)*NFREQ + (size_t)(n*HOP_ + f))*TLEN
                            + (size_t)(t0 + row0))*2 + ri;
            #pragma unroll
            for (int r = 0; r < 8; r++) {
                float a = aa[r][j] + ba_[j];
                float g = ag[r][j] + bg_[j];
                float m = a * fwv / (1.0f + expf(-g));
                atomicAdd(out + obase + (size_t)r*2, m);
            }
        }
    }

    // Remainder cols 512..515 (one output per lane: 8 rows x 4 cols)
    {
        const int j   = lane & 3;
        const int r   = lane >> 2;
        const int col = 512 + j;
        const int row = row0 + r;
        float aa = 0.f, ag = 0.f;
        #pragma unroll 4
        for (int k = 0; k < MLPD; k++) {
            float hv = h_s[row*MLPD + k];
            const float* wrow = W2n + (size_t)k*(2*OUTC);
            aa += hv * wrow[col];
            ag += hv * wrow[OUTC + col];
        }
        float a = aa + b2n[col];
        float g = ag + b2n[OUTC + col];
        int rem = col - 258;          // channel c = 1 for cols 512..515
        int f   = rem >> 1;
        int ri  = rem & 1;
        float m = a * fwn[f] / (1.0f + expf(-g));
        size_t oidx = (((size_t)(b*2 + 1)*NFREQ + (size_t)(n*HOP_ + f))*TLEN
                       + (size_t)(t0 + row))*2 + ri;
        atomicAdd(out + oidx, m);
    }
}

extern "C" void kernel_launch(void* const* d_in, const int* in_sizes, int n_in,
                              void* d_out, int out_size) {
    const float* q        = (const float*)d_in[0];
    const float* ln_gamma = (const float*)d_in[1];
    const float* ln_beta  = (const float*)d_in[2];
    const float* W1       = (const float*)d_in[3];
    const float* b1       = (const float*)d_in[4];
    const float* W2       = (const float*)d_in[5];
    const float* b2       = (const float*)d_in[6];
    const float* fw       = (const float*)d_in[7];
    float* out = (float*)d_out;

    int B = in_sizes[0] / (N_BANDS * TLEN * EMB);

    cudaFuncSetAttribute(omem_band_mlp_kernel,
                         cudaFuncAttributeMaxDynamicSharedMemorySize, SMEM_BYTES);

    int n4 = out_size / 4;
    int zblocks = (n4 + 255) / 256;
    if (zblocks > 16384) zblocks = 16384;
    omem_zero_kernel<<<zblocks, 256>>>((float4*)out, n4);

    dim3 grid(TLEN / TM, N_BANDS, B);
    omem_band_mlp_kernel<<<grid, NTHREADS, SMEM_BYTES>>>(
        q, ln_gamma, ln_beta, W1, b1, W2, b2, fw, out);
}

// round 2
// speedup vs baseline: 1.7005x; 1.7005x over previous
#include <cuda_runtime.h>
#include <math.h>

#define N_BANDS 15
#define BW_     129
#define HOP_    64
#define NFREQ   1025
#define EMB     128
#define MLPD    512
#define OUTC    516      // BW*C*REIM
#define TLEN    2048
#define TM      64
#define NW      16
#define ROWS    4        // rows per warp
#define NTHREADS 512
#define SMEM_BYTES ((TM*EMB + TM*MLPD)*4)   // 32KB qn + 128KB h = 160KB

__global__ void omem_zero_kernel(float4* __restrict__ out, int n4) {
    int i = blockIdx.x*blockDim.x + threadIdx.x;
    int stride = gridDim.x*blockDim.x;
    float4 z = make_float4(0.f,0.f,0.f,0.f);
    for (; i < n4; i += stride) out[i] = z;
}

__global__ __launch_bounds__(NTHREADS, 1)
void omem_band_mlp_kernel(const float* __restrict__ q,
                          const float* __restrict__ ln_gamma,
                          const float* __restrict__ ln_beta,
                          const float* __restrict__ W1,
                          const float* __restrict__ b1,
                          const float* __restrict__ W2,
                          const float* __restrict__ b2,
                          const float* __restrict__ fw,
                          float* __restrict__ out) {
    extern __shared__ float sm[];
    float* qn_s = sm;               // [TM][EMB]
    float* h_s  = sm + TM*EMB;      // [TM][MLPD]

    const int b  = blockIdx.z;
    const int n  = blockIdx.y;
    const int t0 = blockIdx.x * TM;
    const int warp = threadIdx.x >> 5;
    const int lane = threadIdx.x & 31;
    const int row0 = warp * ROWS;

    // ---------------- LayerNorm (warp-per-token) ----------------
    const float* qb = q + ((size_t)(b*N_BANDS + n)*TLEN + t0)*EMB;
    float4 gg  = ((const float4*)(ln_gamma + (size_t)n*EMB))[lane];
    float4 bet = ((const float4*)(ln_beta  + (size_t)n*EMB))[lane];
    for (int i = warp; i < TM; i += NW) {
        float4 v = ((const float4*)(qb + (size_t)i*EMB))[lane];
        float s  = v.x + v.y + v.z + v.w;
        float s2 = v.x*v.x + v.y*v.y + v.z*v.z + v.w*v.w;
        #pragma unroll
        for (int off = 16; off; off >>= 1) {
            s  += __shfl_xor_sync(0xffffffffu, s,  off);
            s2 += __shfl_xor_sync(0xffffffffu, s2, off);
        }
        float mu  = s  * (1.0f/EMB);
        float var = s2 * (1.0f/EMB) - mu*mu;
        float rs  = rsqrtf(var + 1e-5f);
        float4 o;
        o.x = (v.x - mu)*rs*gg.x + bet.x;
        o.y = (v.y - mu)*rs*gg.y + bet.y;
        o.z = (v.z - mu)*rs*gg.z + bet.z;
        o.w = (v.w - mu)*rs*gg.w + bet.w;
        ((float4*)(qn_s + i*EMB))[lane] = o;
    }
    __syncthreads();

    // ---------------- GEMM1: h = tanh(qn @ W1 + b1) ----------------
    const float* W1n = W1 + (size_t)n*EMB*MLPD;
    const float* b1n = b1 + (size_t)n*MLPD;
    #pragma unroll 1
    for (int c0 = 0; c0 < MLPD; c0 += 128) {
        const int col = c0 + lane*4;
        float acc[ROWS][4];
        #pragma unroll
        for (int r = 0; r < ROWS; r++) { acc[r][0]=0.f; acc[r][1]=0.f; acc[r][2]=0.f; acc[r][3]=0.f; }
        #pragma unroll 2
        for (int k4 = 0; k4 < EMB; k4 += 4) {
            float4 hv[ROWS];
            #pragma unroll
            for (int r = 0; r < ROWS; r++)
                hv[r] = *(const float4*)(qn_s + (row0+r)*EMB + k4);  // broadcast
            #pragma unroll
            for (int kk = 0; kk < 4; kk++) {
                float4 w = *(const float4*)(W1n + (size_t)(k4+kk)*MLPD + col);
                #pragma unroll
                for (int r = 0; r < ROWS; r++) {
                    float hvv = ((const float*)&hv[r])[kk];
                    acc[r][0] += hvv*w.x; acc[r][1] += hvv*w.y;
                    acc[r][2] += hvv*w.z; acc[r][3] += hvv*w.w;
                }
            }
        }
        float4 bias = *(const float4*)(b1n + col);
        #pragma unroll
        for (int r = 0; r < ROWS; r++) {
            float4 o;
            o.x = tanhf(acc[r][0] + bias.x);
            o.y = tanhf(acc[r][1] + bias.y);
            o.z = tanhf(acc[r][2] + bias.z);
            o.w = tanhf(acc[r][3] + bias.w);
            *(float4*)(h_s + (row0+r)*MLPD + col) = o;
        }
    }
    __syncthreads();

    // ---------------- GEMM2 (paired a/g cols) + gate + scatter ----------------
    const float* W2n = W2 + (size_t)n*MLPD*(2*OUTC);
    const float* b2n = b2 + (size_t)n*(2*OUTC);
    const float* fwn = fw + (size_t)n*BW_;

    #pragma unroll 1
    for (int c0 = 0; c0 < 512; c0 += 128) {
        const int col = c0 + lane*4;
        float aa[ROWS][4], ag[ROWS][4];
        #pragma unroll
        for (int r = 0; r < ROWS; r++) {
            aa[r][0]=0.f; aa[r][1]=0.f; aa[r][2]=0.f; aa[r][3]=0.f;
            ag[r][0]=0.f; ag[r][1]=0.f; ag[r][2]=0.f; ag[r][3]=0.f;
        }
        #pragma unroll 1
        for (int k4 = 0; k4 < MLPD; k4 += 4) {
            float4 hv[ROWS];
            #pragma unroll
            for (int r = 0; r < ROWS; r++)
                hv[r] = *(const float4*)(h_s + (row0+r)*MLPD + k4);  // broadcast
            #pragma unroll
            for (int kk = 0; kk < 4; kk++) {
                const float* wrow = W2n + (size_t)(k4+kk)*(2*OUTC);
                float4 wa = *(const float4*)(wrow + col);
                float4 wg = *(const float4*)(wrow + OUTC + col);
                #pragma unroll
                for (int r = 0; r < ROWS; r++) {
                    float hvv = ((const float*)&hv[r])[kk];
                    aa[r][0] += hvv*wa.x; aa[r][1] += hvv*wa.y;
                    aa[r][2] += hvv*wa.z; aa[r][3] += hvv*wa.w;
                    ag[r][0] += hvv*wg.x; ag[r][1] += hvv*wg.y;
                    ag[r][2] += hvv*wg.z; ag[r][3] += hvv*wg.w;
                }
            }
        }
        float4 ba4 = *(const float4*)(b2n + col);
        float4 bg4 = *(const float4*)(b2n + OUTC + col);
        float ba_[4] = {ba4.x, ba4.y, ba4.z, ba4.w};
        float bg_[4] = {bg4.x, bg4.y, bg4.z, bg4.w};
        #pragma unroll
        for (int j = 0; j < 4; j++) {
            int cj  = col + j;
            int c   = (cj >= 258) ? 1 : 0;
            int rem = cj - c*258;
            int f   = rem >> 1;
            int ri  = rem & 1;
            float fwv = fwn[f];
            size_t obase = (((size_t)(b*2 + c)*NFREQ + (size_t)(n*HOP_ + f))*TLEN
                            + (size_t)(t0 + row0))*2 + ri;
            #pragma unroll
            for (int r = 0; r < ROWS; r++) {
                float a = aa[r][j] + ba_[j];
                float g = ag[r][j] + bg_[j];
                float m = a * fwv / (1.0f + expf(-g));
                atomicAdd(out + obase + (size_t)r*2, m);
            }
        }
    }

    // Remainder cols 512..515: 4 rows x 4 cols per warp; lanes split K in halves.
    {
        const int j     = lane & 3;
        const int r     = (lane >> 2) & 3;
        const int khalf = lane >> 4;          // 0 or 1
        const int col   = 512 + j;
        const int row   = row0 + r;
        float aa = 0.f, ag = 0.f;
        const int kbeg = khalf * 256;
        #pragma unroll 4
        for (int k = kbeg; k < kbeg + 256; k++) {
            float hv = h_s[row*MLPD + k];
            const float* wrow = W2n + (size_t)k*(2*OUTC);
            aa += hv * wrow[col];
            ag += hv * wrow[OUTC + col];
        }
        aa += __shfl_xor_sync(0xffffffffu, aa, 16);
        ag += __shfl_xor_sync(0xffffffffu, ag, 16);
        if (khalf == 0) {
            float a = aa + b2n[col];
            float g = ag + b2n[OUTC + col];
            int rem = col - 258;          // channel c = 1 for cols 512..515
            int f   = rem >> 1;
            int ri  = rem & 1;
            float m = a * fwn[f] / (1.0f + expf(-g));
            size_t oidx = (((size_t)(b*2 + 1)*NFREQ + (size_t)(n*HOP_ + f))*TLEN
                           + (size_t)(t0 + row))*2 + ri;
            atomicAdd(out + oidx, m);
        }
    }
}

extern "C" void kernel_launch(void* const* d_in, const int* in_sizes, int n_in,
                              void* d_out, int out_size) {
    const float* q        = (const float*)d_in[0];
    const float* ln_gamma = (const float*)d_in[1];
    const float* ln_beta  = (const float*)d_in[2];
    const float* W1       = (const float*)d_in[3];
    const float* b1       = (const float*)d_in[4];
    const float* W2       = (const float*)d_in[5];
    const float* b2       = (const float*)d_in[6];
    const float* fw       = (const float*)d_in[7];
    float* out = (float*)d_out;

    int B = in_sizes[0] / (N_BANDS * TLEN * EMB);

    cudaFuncSetAttribute(omem_band_mlp_kernel,
                         cudaFuncAttributeMaxDynamicSharedMemorySize, SMEM_BYTES);

    int n4 = out_size / 4;
    int zblocks = (n4 + 255) / 256;
    if (zblocks > 16384) zblocks = 16384;
    omem_zero_kernel<<<zblocks, 256>>>((float4*)out, n4);

    dim3 grid(TLEN / TM, N_BANDS, B);
    omem_band_mlp_kernel<<<grid, NTHREADS, SMEM_BYTES>>>(
        q, ln_gamma, ln_beta, W1, b1, W2, b2, fw, out);
}

// round 3
// speedup vs baseline: 2.2519x; 1.3242x over previous
#include <cuda_runtime.h>
#include <cuda_fp16.h>
#include <math.h>

#define N_BANDS 15
#define BW_     129
#define HOP_    64
#define NFREQ   1025
#define EMB     128
#define MLPD    512
#define OUTC    516      // BW*C*REIM
#define TLEN    2048
#define TM      64
#define NW      8
#define ROWS    8        // rows per warp
#define NTHREADS 256
// qn fp32 (32KB) + h fp16 (64KB) = 96KB -> 2 CTAs/SM
#define SMEM_BYTES (TM*EMB*4 + TM*MLPD*2)

__global__ void omem_zero_kernel(float4* __restrict__ out, int n4) {
    int i = blockIdx.x*blockDim.x + threadIdx.x;
    int stride = gridDim.x*blockDim.x;
    float4 z = make_float4(0.f,0.f,0.f,0.f);
    for (; i < n4; i += stride) out[i] = z;
}

__global__ __launch_bounds__(NTHREADS, 2)
void omem_band_mlp_kernel(const float* __restrict__ q,
                          const float* __restrict__ ln_gamma,
                          const float* __restrict__ ln_beta,
                          const float* __restrict__ W1,
                          const float* __restrict__ b1,
                          const float* __restrict__ W2,
                          const float* __restrict__ b2,
                          const float* __restrict__ fw,
                          float* __restrict__ out) {
    extern __shared__ float sm[];
    float*  qn_s = sm;                         // [TM][EMB] fp32
    __half* h_s  = (__half*)(sm + TM*EMB);     // [TM][MLPD] fp16

    const int b  = blockIdx.z;
    const int n  = blockIdx.y;
    const int t0 = blockIdx.x * TM;
    const int warp = threadIdx.x >> 5;
    const int lane = threadIdx.x & 31;
    const int row0 = warp * ROWS;

    // ---------------- LayerNorm (warp-per-token) ----------------
    const float* qb = q + ((size_t)(b*N_BANDS + n)*TLEN + t0)*EMB;
    float4 gg  = ((const float4*)(ln_gamma + (size_t)n*EMB))[lane];
    float4 bet = ((const float4*)(ln_beta  + (size_t)n*EMB))[lane];
    for (int i = warp; i < TM; i += NW) {
        float4 v = ((const float4*)(qb + (size_t)i*EMB))[lane];
        float s  = v.x + v.y + v.z + v.w;
        float s2 = v.x*v.x + v.y*v.y + v.z*v.z + v.w*v.w;
        #pragma unroll
        for (int off = 16; off; off >>= 1) {
            s  += __shfl_xor_sync(0xffffffffu, s,  off);
            s2 += __shfl_xor_sync(0xffffffffu, s2, off);
        }
        float mu  = s  * (1.0f/EMB);
        float var = s2 * (1.0f/EMB) - mu*mu;
        float rs  = rsqrtf(var + 1e-5f);
        float4 o;
        o.x = (v.x - mu)*rs*gg.x + bet.x;
        o.y = (v.y - mu)*rs*gg.y + bet.y;
        o.z = (v.z - mu)*rs*gg.z + bet.z;
        o.w = (v.w - mu)*rs*gg.w + bet.w;
        ((float4*)(qn_s + i*EMB))[lane] = o;
    }
    __syncthreads();

    // ---------------- GEMM1: h = tanh(qn @ W1 + b1) -> fp16 smem ----------------
    const float* W1n = W1 + (size_t)n*EMB*MLPD;
    const float* b1n = b1 + (size_t)n*MLPD;
    #pragma unroll 1
    for (int c0 = 0; c0 < MLPD; c0 += 128) {
        const int col = c0 + lane*4;
        float acc[ROWS][4];
        #pragma unroll
        for (int r = 0; r < ROWS; r++) { acc[r][0]=0.f; acc[r][1]=0.f; acc[r][2]=0.f; acc[r][3]=0.f; }
        #pragma unroll 1
        for (int k4 = 0; k4 < EMB; k4 += 4) {
            float4 hv[ROWS];
            #pragma unroll
            for (int r = 0; r < ROWS; r++)
                hv[r] = *(const float4*)(qn_s + (row0+r)*EMB + k4);  // broadcast
            #pragma unroll
            for (int kk = 0; kk < 4; kk++) {
                float4 w = *(const float4*)(W1n + (size_t)(k4+kk)*MLPD + col);
                #pragma unroll
                for (int r = 0; r < ROWS; r++) {
                    float hvv = ((const float*)&hv[r])[kk];
                    acc[r][0] += hvv*w.x; acc[r][1] += hvv*w.y;
                    acc[r][2] += hvv*w.z; acc[r][3] += hvv*w.w;
                }
            }
        }
        float4 bias = *(const float4*)(b1n + col);
        #pragma unroll
        for (int r = 0; r < ROWS; r++) {
            float ox = tanhf(acc[r][0] + bias.x);
            float oy = tanhf(acc[r][1] + bias.y);
            float oz = tanhf(acc[r][2] + bias.z);
            float ow = tanhf(acc[r][3] + bias.w);
            __half2 p0 = __floats2half2_rn(ox, oy);
            __half2 p1 = __floats2half2_rn(oz, ow);
            uint2 packed;
            packed.x = *(unsigned*)&p0;
            packed.y = *(unsigned*)&p1;
            *(uint2*)(h_s + (row0+r)*MLPD + col) = packed;
        }
    }
    __syncthreads();

    // ---------------- GEMM2 (paired a/g cols) + gate + scatter ----------------
    const float* W2n = W2 + (size_t)n*MLPD*(2*OUTC);
    const float* b2n = b2 + (size_t)n*(2*OUTC);
    const float* fwn = fw + (size_t)n*BW_;

    #pragma unroll 1
    for (int c0 = 0; c0 < 512; c0 += 128) {
        const int col = c0 + lane*4;
        float aa[ROWS][4], ag[ROWS][4];
        #pragma unroll
        for (int r = 0; r < ROWS; r++) {
            aa[r][0]=0.f; aa[r][1]=0.f; aa[r][2]=0.f; aa[r][3]=0.f;
            ag[r][0]=0.f; ag[r][1]=0.f; ag[r][2]=0.f; ag[r][3]=0.f;
        }
        #pragma unroll 1
        for (int k4 = 0; k4 < MLPD; k4 += 4) {
            float hv[ROWS][4];
            #pragma unroll
            for (int r = 0; r < ROWS; r++) {
                uint2 hraw = *(const uint2*)(h_s + (row0+r)*MLPD + k4);  // broadcast LDS.64
                float2 f01 = __half22float2(*(__half2*)&hraw.x);
                float2 f23 = __half22float2(*(__half2*)&hraw.y);
                hv[r][0]=f01.x; hv[r][1]=f01.y; hv[r][2]=f23.x; hv[r][3]=f23.y;
            }
            #pragma unroll
            for (int kk = 0; kk < 4; kk++) {
                const float* wrow = W2n + (size_t)(k4+kk)*(2*OUTC);
                float4 wa = *(const float4*)(wrow + col);
                float4 wg = *(const float4*)(wrow + OUTC + col);
                #pragma unroll
                for (int r = 0; r < ROWS; r++) {
                    float hvv = hv[r][kk];
                    aa[r][0] += hvv*wa.x; aa[r][1] += hvv*wa.y;
                    aa[r][2] += hvv*wa.z; aa[r][3] += hvv*wa.w;
                    ag[r][0] += hvv*wg.x; ag[r][1] += hvv*wg.y;
                    ag[r][2] += hvv*wg.z; ag[r][3] += hvv*wg.w;
                }
            }
        }
        float4 ba4 = *(const float4*)(b2n + col);
        float4 bg4 = *(const float4*)(b2n + OUTC + col);
        float ba_[4] = {ba4.x, ba4.y, ba4.z, ba4.w};
        float bg_[4] = {bg4.x, bg4.y, bg4.z, bg4.w};
        #pragma unroll
        for (int j = 0; j < 4; j++) {
            int cj  = col + j;
            int c   = (cj >= 258) ? 1 : 0;
            int rem = cj - c*258;
            int f   = rem >> 1;
            int ri  = rem & 1;
            float fwv = fwn[f];
            size_t obase = (((size_t)(b*2 + c)*NFREQ + (size_t)(n*HOP_ + f))*TLEN
                            + (size_t)(t0 + row0))*2 + ri;
            #pragma unroll
            for (int r = 0; r < ROWS; r++) {
                float a = aa[r][j] + ba_[j];
                float g = ag[r][j] + bg_[j];
                float m = a * fwv / (1.0f + __expf(-g));
                atomicAdd(out + obase + (size_t)r*2, m);
            }
        }
    }

    // Remainder cols 512..515: one output per lane (8 rows x 4 cols)
    {
        const int j   = lane & 3;
        const int r   = lane >> 2;
        const int col = 512 + j;
        const int row = row0 + r;
        float aa = 0.f, ag = 0.f;
        #pragma unroll 4
        for (int k = 0; k < MLPD; k++) {
            float hvv = __half2float(h_s[row*MLPD + k]);
            const float* wrow = W2n + (size_t)k*(2*OUTC);
            aa += hvv * wrow[col];
            ag += hvv * wrow[OUTC + col];
        }
        float a = aa + b2n[col];
        float g = ag + b2n[OUTC + col];
        int rem = col - 258;          // channel c = 1 for cols 512..515
        int f   = rem >> 1;
        int ri  = rem & 1;
        float m = a * fwn[f] / (1.0f + __expf(-g));
        size_t oidx = (((size_t)(b*2 + 1)*NFREQ + (size_t)(n*HOP_ + f))*TLEN
                       + (size_t)(t0 + row))*2 + ri;
        atomicAdd(out + oidx, m);
    }
}

extern "C" void kernel_launch(void* const* d_in, const int* in_sizes, int n_in,
                              void* d_out, int out_size) {
    const float* q        = (const float*)d_in[0];
    const float* ln_gamma = (const float*)d_in[1];
    const float* ln_beta  = (const float*)d_in[2];
    const float* W1       = (const float*)d_in[3];
    const float* b1       = (const float*)d_in[4];
    const float* W2       = (const float*)d_in[5];
    const float* b2       = (const float*)d_in[6];
    const float* fw       = (const float*)d_in[7];
    float* out = (float*)d_out;

    int B = in_sizes[0] / (N_BANDS * TLEN * EMB);

    cudaFuncSetAttribute(omem_band_mlp_kernel,
                         cudaFuncAttributeMaxDynamicSharedMemorySize, SMEM_BYTES);

    int n4 = out_size / 4;
    int zblocks = (n4 + 255) / 256;
    if (zblocks > 16384) zblocks = 16384;
    omem_zero_kernel<<<zblocks, 256>>>((float4*)out, n4);

    dim3 grid(TLEN / TM, N_BANDS, B);
    omem_band_mlp_kernel<<<grid, NTHREADS, SMEM_BYTES>>>(
        q, ln_gamma, ln_beta, W1, b1, W2, b2, fw, out);
}

// round 5
// speedup vs baseline: 7.0246x; 3.1194x over previous
#include <cuda_runtime.h>
#include <cuda_fp16.h>
#include <stdint.h>
#include <math.h>

#define N_BANDS 15
#define BW_     129
#define HOP_    64
#define NFREQ   1025
#define EMB     128
#define MLPD    512
#define TLEN    2048
#define TMK     128
#define NTH     256
#define W2ROWS  1032
#define W2PAD   1056          // padded to 33 uniform chunks of 32
#define NCH2    33

// smem layout (bytes)
#define AH_OFF   0            // h fp16 [128][512] swizzled = 131072
#define STG_OFF  131072       // 2 x 32768 staging buffers
#define AQN_OFF  196608       // qn fp16 [128][128] swizzled = 32768
#define SMEM_TOTAL 229376

// preconverted weights (rebuilt every launch — deterministic)
__device__ __align__(16) __half g_W1T[(size_t)N_BANDS * MLPD * EMB];     // [n][o][k]
__device__ __align__(16) __half g_W2T[(size_t)N_BANDS * W2PAD * MLPD];   // [n][row][k] interleaved a/g, fw folded, zero-padded
__device__ float g_b2i[N_BANDS * W2ROWS];                                // interleaved biases, a scaled by fw

__device__ __forceinline__ uint32_t smem_u32(const void* p){
    uint32_t a;
    asm("{ .reg .u64 t; cvta.to.shared.u64 t, %1; cvt.u32.u64 %0, t; }" : "=r"(a) : "l"(p));
    return a;
}
__device__ __forceinline__ void ldsm4(uint32_t* r, uint32_t a){
    asm volatile("ldmatrix.sync.aligned.m8n8.x4.shared.b16 {%0,%1,%2,%3}, [%4];"
        : "=r"(r[0]),"=r"(r[1]),"=r"(r[2]),"=r"(r[3]) : "r"(a));
}
__device__ __forceinline__ void mma16816(float* c, const uint32_t* a, uint32_t b0, uint32_t b1){
    asm volatile("mma.sync.aligned.m16n8k16.row.col.f32.f16.f16.f32 "
        "{%0,%1,%2,%3}, {%4,%5,%6,%7}, {%8,%9}, {%0,%1,%2,%3};"
        : "+f"(c[0]),"+f"(c[1]),"+f"(c[2]),"+f"(c[3])
        : "r"(a[0]),"r"(a[1]),"r"(a[2]),"r"(a[3]),"r"(b0),"r"(b1));
}
__device__ __forceinline__ uint32_t f2h2(float a, float b){
    __half2 h = __floats2half2_rn(a, b);
    return *(uint32_t*)&h;
}

// ---------------- prep kernels ----------------
__global__ void prep_w1(const float* __restrict__ W1, const float* __restrict__ b2,
                        const float* __restrict__ fw){
    int idx = blockIdx.x * blockDim.x + threadIdx.x;
    if (idx < N_BANDS * MLPD * EMB){
        int k = idx & 127, o = (idx >> 7) & 511, n = idx >> 16;
        g_W1T[idx] = __float2half(W1[((size_t)n * EMB + k) * MLPD + o]);
    }
    if (idx < N_BANDS * W2ROWS){
        int r = idx % W2ROWS, n = idx / W2ROWS;
        int j = r >> 1, gbit = r & 1;
        float v = b2[(size_t)n * W2ROWS + (gbit ? j + 516 : j)];
        if (!gbit){
            int cc = j >= 258; int rem = j - cc * 258;
            v *= fw[n * BW_ + (rem >> 1)];
        }
        g_b2i[idx] = v;
    }
}
__global__ void prep_w2(const float* __restrict__ W2, const float* __restrict__ fw){
    int idx = blockIdx.x * blockDim.x + threadIdx.x;
    if (idx >= N_BANDS * W2PAD * MLPD) return;
    int k = idx & 511;
    int r = (idx >> 9) % W2PAD;
    int n = idx / (W2PAD * MLPD);
    float v = 0.0f;
    if (r < W2ROWS){
        int j = r >> 1, gbit = r & 1;
        int src_o = gbit ? j + 516 : j;
        v = W2[((size_t)n * MLPD + k) * W2ROWS + src_o];
        if (!gbit){
            int cc = j >= 258; int rem = j - cc * 258;
            v *= fw[n * BW_ + (rem >> 1)];
        }
    }
    g_W2T[(size_t)n * W2PAD * MLPD + (size_t)r * MLPD + k] = __float2half(v);
}
__global__ void omem_zero_kernel(float4* __restrict__ out, int n4){
    int i = blockIdx.x * blockDim.x + threadIdx.x;
    int stride = gridDim.x * blockDim.x;
    float4 z = make_float4(0.f, 0.f, 0.f, 0.f);
    for (; i < n4; i += stride) out[i] = z;
}

// ---------------- main kernel ----------------
__global__ __launch_bounds__(NTH)
void omem_hmma_kernel(const float* __restrict__ q,
                      const float* __restrict__ ln_gamma,
                      const float* __restrict__ ln_beta,
                      const float* __restrict__ b1,
                      float* __restrict__ out){
    extern __shared__ __align__(1024) char smem[];
    const uint32_t sb = smem_u32(smem);
    const int tid = threadIdx.x, warp = tid >> 5, lane = tid & 31;
    const int b = blockIdx.z, n = blockIdx.y, t0 = blockIdx.x * TMK;

    // ---- LayerNorm -> qn fp16, swizzled [128][256B] ----
    {
        const float* qb = q + ((size_t)(b * N_BANDS + n) * TLEN + t0) * EMB;
        float4 gg  = ((const float4*)(ln_gamma + (size_t)n * EMB))[lane];
        float4 bet = ((const float4*)(ln_beta  + (size_t)n * EMB))[lane];
        for (int i = warp; i < TMK; i += 8){
            float4 v = ((const float4*)(qb + (size_t)i * EMB))[lane];
            float s  = v.x + v.y + v.z + v.w;
            float s2 = v.x*v.x + v.y*v.y + v.z*v.z + v.w*v.w;
            #pragma unroll
            for (int off = 16; off; off >>= 1){
                s  += __shfl_xor_sync(0xffffffffu, s,  off);
                s2 += __shfl_xor_sync(0xffffffffu, s2, off);
            }
            float mu = s * (1.0f/EMB);
            float var = s2 * (1.0f/EMB) - mu*mu;
            float rs = rsqrtf(var + 1e-5f);
            uint2 pk;
            pk.x = f2h2((v.x - mu)*rs*gg.x + bet.x, (v.y - mu)*rs*gg.y + bet.y);
            pk.y = f2h2((v.z - mu)*rs*gg.z + bet.z, (v.w - mu)*rs*gg.w + bet.w);
            uint32_t ch = (uint32_t)(lane >> 1) ^ (uint32_t)(i & 7);
            *(uint2*)(smem + AQN_OFF + i * 256 + ch * 16 + (lane & 1) * 8) = pk;
        }
    }
    __syncthreads();

    // ldmatrix lane-address components (shared by both GEMMs)
    const uint32_t aRow = warp * 16 + (lane & 15);
    const uint32_t aS   = aRow & 7;
    const uint32_t aHi  = lane >> 4;                        // +16B half of k16
    const uint32_t bRowL = (lane & 7) | ((lane & 16) >> 1); // 0..15
    const uint32_t bHi   = (lane >> 3) & 1;
    const uint32_t bS    = bRowL & 7;

    // ---- GEMM1: z = qn @ W1T^T (M=128,K=128,N=512), 16 chunks of 32 rows ----
    {
        const __half* W1Tn = g_W1T + (size_t)n * MLPD * EMB;
        const float*  b1n  = b1 + (size_t)n * MLPD;
        const uint32_t aBase = sb + AQN_OFF + aRow * 256;
        uint4 st[2];
        // preload + store chunk 0 into buf 0
        {
            const uint4* src = (const uint4*)W1Tn;
            #pragma unroll
            for (int i = 0; i < 2; i++) st[i] = src[i * NTH + tid];
            #pragma unroll
            for (int i = 0; i < 2; i++){
                int lin = i * NTH + tid; int r = lin >> 4, cn = lin & 15;
                *(uint4*)(smem + STG_OFF + r * 256 + (((uint32_t)cn ^ (r & 7)) << 4)) = st[i];
            }
        }
        __syncthreads();
        #pragma unroll 1
        for (int c = 0; c < 16; c++){
            const int cbuf = c & 1, nbuf = (c + 1) & 1;
            if (c + 1 < 16){
                const uint4* src = (const uint4*)(W1Tn + (size_t)(c + 1) * 32 * EMB);
                #pragma unroll
                for (int i = 0; i < 2; i++) st[i] = src[i * NTH + tid];
            }
            float acc[4][4];
            #pragma unroll
            for (int t = 0; t < 4; t++){ acc[t][0]=0.f; acc[t][1]=0.f; acc[t][2]=0.f; acc[t][3]=0.f; }
            const uint32_t sB0 = sb + STG_OFF + cbuf * 32768 + bRowL * 256;
            const uint32_t sB1 = sB0 + 16 * 256;
            #pragma unroll
            for (int ks = 0; ks < 8; ks++){
                uint32_t a[4], b0r[4], b1r[4];
                ldsm4(a,   aBase + ((((2*ks) + aHi) ^ aS) << 4));
                ldsm4(b0r, sB0   + ((((2*ks) + bHi) ^ bS) << 4));
                ldsm4(b1r, sB1   + ((((2*ks) + bHi) ^ bS) << 4));
                mma16816(acc[0], a, b0r[0], b0r[1]);
                mma16816(acc[1], a, b0r[2], b0r[3]);
                mma16816(acc[2], a, b1r[0], b1r[1]);
                mma16816(acc[3], a, b1r[2], b1r[3]);
            }
            // epilogue: tanh -> h smem (swizzled [128][1024B])
            const uint32_t hr0 = warp * 16 + (lane >> 2);
            const uint32_t hr1 = hr0 + 8;
            #pragma unroll
            for (int t = 0; t < 4; t++){
                int ng = c * 32 + t * 8 + 2 * (lane & 3);
                float2 bb = *(const float2*)(b1n + ng);
                uint32_t p0 = f2h2(tanhf(acc[t][0] + bb.x), tanhf(acc[t][1] + bb.y));
                uint32_t p1 = f2h2(tanhf(acc[t][2] + bb.x), tanhf(acc[t][3] + bb.y));
                uint32_t nbyte = (uint32_t)ng * 2u;
                uint32_t ch = nbyte >> 4, sub = nbyte & 15;
                *(uint32_t*)(smem + AH_OFF + hr0 * 1024 + ((ch ^ (hr0 & 7)) << 4) + sub) = p0;
                *(uint32_t*)(smem + AH_OFF + hr1 * 1024 + ((ch ^ (hr1 & 7)) << 4) + sub) = p1;
            }
            if (c + 1 < 16){
                #pragma unroll
                for (int i = 0; i < 2; i++){
                    int lin = i * NTH + tid; int r = lin >> 4, cn = lin & 15;
                    *(uint4*)(smem + STG_OFF + nbuf * 32768 + r * 256 + (((uint32_t)cn ^ (r & 7)) << 4)) = st[i];
                }
            }
            __syncthreads();
        }
    }

    // ---- GEMM2: o = h @ W2T^T (M=128,K=512,Npad=1056), 33 chunks of 32 rows ----
    {
        const __half* W2Tn = g_W2T + (size_t)n * W2PAD * MLPD;
        const float*  b2in = g_b2i + n * W2ROWS;
        const uint32_t aBase = sb + AH_OFF + aRow * 1024;
        uint4 st[8];
        // preload + store chunk 0 into buf 0
        {
            const uint4* src = (const uint4*)W2Tn;
            #pragma unroll
            for (int i = 0; i < 8; i++) st[i] = src[i * NTH + tid];
            #pragma unroll
            for (int i = 0; i < 8; i++){
                int lin = i * NTH + tid; int r = lin >> 6, cn = lin & 63;
                *(uint4*)(smem + STG_OFF + r * 1024 + (((uint32_t)cn ^ (r & 7)) << 4)) = st[i];
            }
        }
        __syncthreads();
        #pragma unroll 1
        for (int c = 0; c < NCH2; c++){
            const int cbuf = c & 1, nbuf = (c + 1) & 1;
            if (c + 1 < NCH2){
                const uint4* src = (const uint4*)(W2Tn + (size_t)(c + 1) * 32 * MLPD);
                #pragma unroll
                for (int i = 0; i < 8; i++) st[i] = src[i * NTH + tid];
            }
            float acc[4][4];
            #pragma unroll
            for (int t = 0; t < 4; t++){ acc[t][0]=0.f; acc[t][1]=0.f; acc[t][2]=0.f; acc[t][3]=0.f; }
            const uint32_t sB0 = sb + STG_OFF + cbuf * 32768 + bRowL * 1024;
            const uint32_t sB1 = sB0 + 16 * 1024;
            #pragma unroll 8
            for (int ks = 0; ks < 32; ks++){
                uint32_t a[4], b0r[4], b1r[4];
                ldsm4(a,   aBase + ((((2*ks) + aHi) ^ aS) << 4));
                ldsm4(b0r, sB0   + ((((2*ks) + bHi) ^ bS) << 4));
                ldsm4(b1r, sB1   + ((((2*ks) + bHi) ^ bS) << 4));
                mma16816(acc[0], a, b0r[0], b0r[1]);
                mma16816(acc[1], a, b0r[2], b0r[3]);
                mma16816(acc[2], a, b1r[0], b1r[1]);
                mma16816(acc[3], a, b1r[2], b1r[3]);
            }
            // epilogue: gate + scatter (a/g interleaved: n even=a, odd=g)
            {
                const int tok0 = t0 + warp * 16 + (lane >> 2);
                #pragma unroll
                for (int t = 0; t < 4; t++){
                    int jp = c * 16 + t * 4 + (lane & 3);
                    if (jp < 516){
                        float2 bb = *(const float2*)(b2in + 2 * jp);
                        int cc = jp >= 258;
                        int rem = jp - cc * 258;
                        int f = rem >> 1, ri = rem & 1;
                        size_t obase = (((size_t)(b * 2 + cc) * NFREQ + (size_t)(n * HOP_ + f)) * TLEN);
                        float a0 = acc[t][0] + bb.x, g0 = acc[t][1] + bb.y;
                        float a1 = acc[t][2] + bb.x, g1 = acc[t][3] + bb.y;
                        atomicAdd(out + (obase + tok0) * 2 + ri,       a0 / (1.0f + __expf(-g0)));
                        atomicAdd(out + (obase + tok0 + 8) * 2 + ri,   a1 / (1.0f + __expf(-g1)));
                    }
                }
            }
            if (c + 1 < NCH2){
                #pragma unroll
                for (int i = 0; i < 8; i++){
                    int lin = i * NTH + tid; int r = lin >> 6, cn = lin & 63;
                    *(uint4*)(smem + STG_OFF + nbuf * 32768 + r * 1024 + (((uint32_t)cn ^ (r & 7)) << 4)) = st[i];
                }
            }
            __syncthreads();
        }
    }
}

extern "C" void kernel_launch(void* const* d_in, const int* in_sizes, int n_in,
                              void* d_out, int out_size){
    const float* q        = (const float*)d_in[0];
    const float* ln_gamma = (const float*)d_in[1];
    const float* ln_beta  = (const float*)d_in[2];
    const float* W1       = (const float*)d_in[3];
    const float* b1       = (const float*)d_in[4];
    const float* W2       = (const float*)d_in[5];
    const float* b2       = (const float*)d_in[6];
    const float* fw       = (const float*)d_in[7];
    float* out = (float*)d_out;

    int B = in_sizes[0] / (N_BANDS * TLEN * EMB);

    {
        int tot1 = N_BANDS * MLPD * EMB;
        prep_w1<<<(tot1 + 255) / 256, 256>>>(W1, b2, fw);
        int tot2 = N_BANDS * W2PAD * MLPD;
        prep_w2<<<(tot2 + 255) / 256, 256>>>(W2, fw);
    }
    {
        int n4 = out_size / 4;
        int zb = (n4 + 255) / 256; if (zb > 16384) zb = 16384;
        omem_zero_kernel<<<zb, 256>>>((float4*)out, n4);
    }
    cudaFuncSetAttribute(omem_hmma_kernel, cudaFuncAttributeMaxDynamicSharedMemorySize, SMEM_TOTAL);
    dim3 grid(TLEN / TMK, N_BANDS, B);
    omem_hmma_kernel<<<grid, NTH, SMEM_TOTAL>>>(q, ln_gamma, ln_beta, b1, out);
}

// round 6
// speedup vs baseline: 7.6607x; 1.0905x over previous
#include <cuda_runtime.h>
#include <cuda_fp16.h>
#include <stdint.h>
#include <math.h>

#define N_BANDS 15
#define BW_     129
#define HOP_    64
#define NFREQ   1025
#define EMB     128
#define MLPD    512
#define TLEN    2048
#define TMK     128
#define NTH     512
#define W2ROWS  1032
#define W2PAD   1056
#define NCH2    33

// smem layout (bytes)
#define AH_OFF   0            // h fp16 [128][512] swizzled = 131072
#define STG_OFF  131072       // staging: GEMM1 2x8192, GEMM2 2x32768
#define AQN_OFF  196608       // qn fp16 [128][128] swizzled = 32768
#define SMEM_TOTAL 229376

__device__ __align__(16) __half g_W1T[(size_t)N_BANDS * MLPD * EMB];
__device__ __align__(16) __half g_W2T[(size_t)N_BANDS * W2PAD * MLPD];
__device__ float g_b2i[N_BANDS * W2ROWS];

__device__ __forceinline__ uint32_t smem_u32(const void* p){
    uint32_t a;
    asm("{ .reg .u64 t; cvta.to.shared.u64 t, %1; cvt.u32.u64 %0, t; }" : "=r"(a) : "l"(p));
    return a;
}
__device__ __forceinline__ void ldsm4(uint32_t* r, uint32_t a){
    asm volatile("ldmatrix.sync.aligned.m8n8.x4.shared.b16 {%0,%1,%2,%3}, [%4];"
        : "=r"(r[0]),"=r"(r[1]),"=r"(r[2]),"=r"(r[3]) : "r"(a));
}
__device__ __forceinline__ void mma16816(float* c, const uint32_t* a, uint32_t b0, uint32_t b1){
    asm volatile("mma.sync.aligned.m16n8k16.row.col.f32.f16.f16.f32 "
        "{%0,%1,%2,%3}, {%4,%5,%6,%7}, {%8,%9}, {%0,%1,%2,%3};"
        : "+f"(c[0]),"+f"(c[1]),"+f"(c[2]),"+f"(c[3])
        : "r"(a[0]),"r"(a[1]),"r"(a[2]),"r"(a[3]),"r"(b0),"r"(b1));
}
__device__ __forceinline__ uint32_t f2h2(float a, float b){
    __half2 h = __floats2half2_rn(a, b);
    return *(uint32_t*)&h;
}
__device__ __forceinline__ void cpa16(uint32_t dst, const void* src){
    asm volatile("cp.async.ca.shared.global [%0], [%1], 16;" :: "r"(dst), "l"(src));
}
__device__ __forceinline__ void cpa_commit(){ asm volatile("cp.async.commit_group;" ::: "memory"); }
__device__ __forceinline__ void cpa_wait0(){ asm volatile("cp.async.wait_group 0;" ::: "memory"); }

// ---------------- prep kernels ----------------
__global__ void prep_w1(const float* __restrict__ W1, const float* __restrict__ b2,
                        const float* __restrict__ fw){
    int idx = blockIdx.x * blockDim.x + threadIdx.x;
    if (idx < N_BANDS * MLPD * EMB){
        int k = idx & 127, o = (idx >> 7) & 511, n = idx >> 16;
        g_W1T[idx] = __float2half(W1[((size_t)n * EMB + k) * MLPD + o]);
    }
    if (idx < N_BANDS * W2ROWS){
        int r = idx % W2ROWS, n = idx / W2ROWS;
        int j = r >> 1, gbit = r & 1;
        float v = b2[(size_t)n * W2ROWS + (gbit ? j + 516 : j)];
        if (!gbit){
            int cc = j >= 258; int rem = j - cc * 258;
            v *= fw[n * BW_ + (rem >> 1)];
        }
        g_b2i[idx] = v;
    }
}
__global__ void prep_w2(const float* __restrict__ W2, const float* __restrict__ fw){
    int idx = blockIdx.x * blockDim.x + threadIdx.x;
    if (idx >= N_BANDS * W2PAD * MLPD) return;
    int k = idx & 511;
    int r = (idx >> 9) % W2PAD;
    int n = idx / (W2PAD * MLPD);
    float v = 0.0f;
    if (r < W2ROWS){
        int j = r >> 1, gbit = r & 1;
        int src_o = gbit ? j + 516 : j;
        v = W2[((size_t)n * MLPD + k) * W2ROWS + src_o];
        if (!gbit){
            int cc = j >= 258; int rem = j - cc * 258;
            v *= fw[n * BW_ + (rem >> 1)];
        }
    }
    g_W2T[(size_t)n * W2PAD * MLPD + (size_t)r * MLPD + k] = __float2half(v);
}
__global__ void omem_zero_kernel(float4* __restrict__ out, int n4){
    int i = blockIdx.x * blockDim.x + threadIdx.x;
    int stride = gridDim.x * blockDim.x;
    float4 z = make_float4(0.f, 0.f, 0.f, 0.f);
    for (; i < n4; i += stride) out[i] = z;
}

// ---------------- main kernel ----------------
__global__ __launch_bounds__(NTH)
void omem_hmma_kernel(const float* __restrict__ q,
                      const float* __restrict__ ln_gamma,
                      const float* __restrict__ ln_beta,
                      const float* __restrict__ b1,
                      float* __restrict__ out){
    extern __shared__ __align__(1024) char smem[];
    const uint32_t sb = smem_u32(smem);
    const int tid = threadIdx.x, warp = tid >> 5, lane = tid & 31;
    const int wm = warp & 7, wn = warp >> 3;   // 8 M-warps x 2 N-groups
    const int b = blockIdx.z, n = blockIdx.y, t0 = blockIdx.x * TMK;

    // ---- LayerNorm -> qn fp16, swizzled [128][256B] ----
    {
        const float* qb = q + ((size_t)(b * N_BANDS + n) * TLEN + t0) * EMB;
        float4 gg  = ((const float4*)(ln_gamma + (size_t)n * EMB))[lane];
        float4 bet = ((const float4*)(ln_beta  + (size_t)n * EMB))[lane];
        for (int i = warp; i < TMK; i += 16){
            float4 v = ((const float4*)(qb + (size_t)i * EMB))[lane];
            float s  = v.x + v.y + v.z + v.w;
            float s2 = v.x*v.x + v.y*v.y + v.z*v.z + v.w*v.w;
            #pragma unroll
            for (int off = 16; off; off >>= 1){
                s  += __shfl_xor_sync(0xffffffffu, s,  off);
                s2 += __shfl_xor_sync(0xffffffffu, s2, off);
            }
            float mu = s * (1.0f/EMB);
            float var = s2 * (1.0f/EMB) - mu*mu;
            float rs = rsqrtf(var + 1e-5f);
            uint2 pk;
            pk.x = f2h2((v.x - mu)*rs*gg.x + bet.x, (v.y - mu)*rs*gg.y + bet.y);
            pk.y = f2h2((v.z - mu)*rs*gg.z + bet.z, (v.w - mu)*rs*gg.w + bet.w);
            uint32_t ch = (uint32_t)(lane >> 1) ^ (uint32_t)(i & 7);
            *(uint2*)(smem + AQN_OFF + i * 256 + ch * 16 + (lane & 1) * 8) = pk;
        }
    }

    // ldmatrix lane-address components
    const uint32_t aRow = wm * 16 + (lane & 15);
    const uint32_t aS   = aRow & 7;
    const uint32_t aHi  = lane >> 4;
    const uint32_t bRowL = (lane & 7) | ((lane & 16) >> 1); // 0..15
    const uint32_t bHi   = (lane >> 3) & 1;
    const uint32_t bS    = bRowL & 7;

    __syncthreads();

    // ---- GEMM1: z = qn @ W1T^T (M=128,K=128,N=512), 16 chunks of 32 rows ----
    {
        const __half* W1Tn = g_W1T + (size_t)n * MLPD * EMB;
        const float*  b1n  = b1 + (size_t)n * MLPD;
        const uint32_t aBase = sb + AQN_OFF + aRow * 256;
        // preload chunk 0 into buf 0 (512 threads x 16B = 8KB exactly)
        {
            int r = tid >> 4, cn = tid & 15;
            cpa16(sb + STG_OFF + r * 256 + (((uint32_t)cn ^ (r & 7)) << 4),
                  W1Tn + (size_t)r * EMB + cn * 8);
            cpa_commit();
            cpa_wait0();
        }
        __syncthreads();
        #pragma unroll 1
        for (int c = 0; c < 16; c++){
            const int cbuf = c & 1, nbuf = (c + 1) & 1;
            if (c + 1 < 16){
                int r = tid >> 4, cn = tid & 15;
                cpa16(sb + STG_OFF + nbuf * 8192 + r * 256 + (((uint32_t)cn ^ (r & 7)) << 4),
                      W1Tn + (size_t)(c + 1) * 32 * EMB + (size_t)r * EMB + cn * 8);
                cpa_commit();
            }
            float acc[2][4];
            #pragma unroll
            for (int t = 0; t < 2; t++){ acc[t][0]=0.f; acc[t][1]=0.f; acc[t][2]=0.f; acc[t][3]=0.f; }
            const uint32_t sB = sb + STG_OFF + cbuf * 8192 + (wn * 16 + bRowL) * 256;
            #pragma unroll
            for (int ks = 0; ks < 8; ks++){
                uint32_t a[4], br[4];
                ldsm4(a,  aBase + ((((2*ks) + aHi) ^ aS) << 4));
                ldsm4(br, sB    + ((((2*ks) + bHi) ^ bS) << 4));
                mma16816(acc[0], a, br[0], br[1]);
                mma16816(acc[1], a, br[2], br[3]);
            }
            // epilogue: tanh -> h smem (swizzled [128][1024B])
            const uint32_t hr0 = wm * 16 + (lane >> 2);
            const uint32_t hr1 = hr0 + 8;
            #pragma unroll
            for (int t = 0; t < 2; t++){
                int ng = c * 32 + wn * 16 + t * 8 + 2 * (lane & 3);
                float2 bb = *(const float2*)(b1n + ng);
                uint32_t p0 = f2h2(tanhf(acc[t][0] + bb.x), tanhf(acc[t][1] + bb.y));
                uint32_t p1 = f2h2(tanhf(acc[t][2] + bb.x), tanhf(acc[t][3] + bb.y));
                uint32_t nbyte = (uint32_t)ng * 2u;
                uint32_t ch = nbyte >> 4, sub = nbyte & 15;
                *(uint32_t*)(smem + AH_OFF + hr0 * 1024 + ((ch ^ (hr0 & 7)) << 4) + sub) = p0;
                *(uint32_t*)(smem + AH_OFF + hr1 * 1024 + ((ch ^ (hr1 & 7)) << 4) + sub) = p1;
            }
            if (c + 1 < 16) cpa_wait0();
            __syncthreads();
        }
    }

    // ---- GEMM2: o = h @ W2T^T (M=128,K=512,Npad=1056), 33 chunks of 32 rows ----
    {
        const __half* W2Tn = g_W2T + (size_t)n * W2PAD * MLPD;
        const float*  b2in = g_b2i + n * W2ROWS;
        const uint32_t aBase = sb + AH_OFF + aRow * 1024;
        // preload chunk 0 (32KB = 4 cp per thread)
        {
            #pragma unroll
            for (int i = 0; i < 4; i++){
                int lin = i * NTH + tid; int r = lin >> 6, cn = lin & 63;
                cpa16(sb + STG_OFF + r * 1024 + (((uint32_t)cn ^ (r & 7)) << 4),
                      W2Tn + (size_t)r * MLPD + cn * 8);
            }
            cpa_commit();
            cpa_wait0();
        }
        __syncthreads();
        #pragma unroll 1
        for (int c = 0; c < NCH2; c++){
            const int cbuf = c & 1, nbuf = (c + 1) & 1;
            if (c + 1 < NCH2){
                const __half* src = W2Tn + (size_t)(c + 1) * 32 * MLPD;
                #pragma unroll
                for (int i = 0; i < 4; i++){
                    int lin = i * NTH + tid; int r = lin >> 6, cn = lin & 63;
                    cpa16(sb + STG_OFF + nbuf * 32768 + r * 1024 + (((uint32_t)cn ^ (r & 7)) << 4),
                          src + (size_t)r * MLPD + cn * 8);
                }
                cpa_commit();
            }
            float acc[2][4];
            #pragma unroll
            for (int t = 0; t < 2; t++){ acc[t][0]=0.f; acc[t][1]=0.f; acc[t][2]=0.f; acc[t][3]=0.f; }
            const uint32_t sB = sb + STG_OFF + cbuf * 32768 + (wn * 16 + bRowL) * 1024;
            #pragma unroll 8
            for (int ks = 0; ks < 32; ks++){
                uint32_t a[4], br[4];
                ldsm4(a,  aBase + ((((2*ks) + aHi) ^ aS) << 4));
                ldsm4(br, sB    + ((((2*ks) + bHi) ^ bS) << 4));
                mma16816(acc[0], a, br[0], br[1]);
                mma16816(acc[1], a, br[2], br[3]);
            }
            // epilogue: gate + scatter (interleaved: even n-col=a, odd=g)
            {
                const int tok0 = t0 + wm * 16 + (lane >> 2);
                #pragma unroll
                for (int t = 0; t < 2; t++){
                    int jp = c * 16 + wn * 8 + t * 4 + (lane & 3);
                    if (jp < 516){
                        float2 bb = *(const float2*)(b2in + 2 * jp);
                        int cc = jp >= 258;
                        int rem = jp - cc * 258;
                        int f = rem >> 1, ri = rem & 1;
                        size_t obase = (((size_t)(b * 2 + cc) * NFREQ + (size_t)(n * HOP_ + f)) * TLEN);
                        float a0 = acc[t][0] + bb.x, g0 = acc[t][1] + bb.y;
                        float a1 = acc[t][2] + bb.x, g1 = acc[t][3] + bb.y;
                        atomicAdd(out + (obase + tok0) * 2 + ri,     a0 / (1.0f + __expf(-g0)));
                        atomicAdd(out + (obase + tok0 + 8) * 2 + ri, a1 / (1.0f + __expf(-g1)));
                    }
                }
            }
            if (c + 1 < NCH2) cpa_wait0();
            __syncthreads();
        }
    }
}

extern "C" void kernel_launch(void* const* d_in, const int* in_sizes, int n_in,
                              void* d_out, int out_size){
    const float* q        = (const float*)d_in[0];
    const float* ln_gamma = (const float*)d_in[1];
    const float* ln_beta  = (const float*)d_in[2];
    const float* W1       = (const float*)d_in[3];
    const float* b1       = (const float*)d_in[4];
    const float* W2       = (const float*)d_in[5];
    const float* b2       = (const float*)d_in[6];
    const float* fw       = (const float*)d_in[7];
    float* out = (float*)d_out;

    int B = in_sizes[0] / (N_BANDS * TLEN * EMB);

    {
        int tot1 = N_BANDS * MLPD * EMB;
        prep_w1<<<(tot1 + 255) / 256, 256>>>(W1, b2, fw);
        int tot2 = N_BANDS * W2PAD * MLPD;
        prep_w2<<<(tot2 + 255) / 256, 256>>>(W2, fw);
    }
    {
        int n4 = out_size / 4;
        int zb = (n4 + 255) / 256; if (zb > 16384) zb = 16384;
        omem_zero_kernel<<<zb, 256>>>((float4*)out, n4);
    }
    cudaFuncSetAttribute(omem_hmma_kernel, cudaFuncAttributeMaxDynamicSharedMemorySize, SMEM_TOTAL);
    dim3 grid(TLEN / TMK, N_BANDS, B);
    omem_hmma_kernel<<<grid, NTH, SMEM_TOTAL>>>(q, ln_gamma, ln_beta, b1, out);
}

// round 7
// speedup vs baseline: 7.6864x; 1.0034x over previous
#include <cuda_runtime.h>
#include <cuda_fp16.h>
#include <stdint.h>
#include <math.h>

#define N_BANDS 15
#define BW_     129
#define HOP_    64
#define NFREQ   1025
#define EMB     128
#define MLPD    512
#define TLEN    2048
#define TMK     128
#define NTH     512
#define W2ROWS  1032
#define W2PAD   1056
#define NCH2    33

// smem layout (bytes)
#define AH_OFF   0            // h fp16 [128][1024B] swizzled = 131072
#define STG_OFF  131072       // staging: 2 x 32768
#define AQN_OFF  196608       // qn during GEMM1; K-combine buffers during GEMM2 (2x16KB)
#define SMEM_TOTAL 229376

__device__ __align__(16) __half g_W1T[(size_t)N_BANDS * MLPD * EMB];
__device__ __align__(16) __half g_W2T[(size_t)N_BANDS * W2PAD * MLPD];
__device__ float g_b2i[N_BANDS * W2ROWS];
__device__ float g_scr[(size_t)2 * N_BANDS * 516 * TLEN];   // [b][n][pair][t]

__device__ __forceinline__ uint32_t smem_u32(const void* p){
    uint32_t a;
    asm("{ .reg .u64 t; cvta.to.shared.u64 t, %1; cvt.u32.u64 %0, t; }" : "=r"(a) : "l"(p));
    return a;
}
__device__ __forceinline__ void ldsm4(uint32_t* r, uint32_t a){
    asm volatile("ldmatrix.sync.aligned.m8n8.x4.shared.b16 {%0,%1,%2,%3}, [%4];"
        : "=r"(r[0]),"=r"(r[1]),"=r"(r[2]),"=r"(r[3]) : "r"(a));
}
__device__ __forceinline__ void mma16816(float* c, const uint32_t* a, uint32_t b0, uint32_t b1){
    asm volatile("mma.sync.aligned.m16n8k16.row.col.f32.f16.f16.f32 "
        "{%0,%1,%2,%3}, {%4,%5,%6,%7}, {%8,%9}, {%0,%1,%2,%3};"
        : "+f"(c[0]),"+f"(c[1]),"+f"(c[2]),"+f"(c[3])
        : "r"(a[0]),"r"(a[1]),"r"(a[2]),"r"(a[3]),"r"(b0),"r"(b1));
}
__device__ __forceinline__ uint32_t f2h2(float a, float b){
    __half2 h = __floats2half2_rn(a, b);
    return *(uint32_t*)&h;
}
__device__ __forceinline__ void cpa16(uint32_t dst, const void* src){
    asm volatile("cp.async.ca.shared.global [%0], [%1], 16;" :: "r"(dst), "l"(src));
}
__device__ __forceinline__ void cpa_commit(){ asm volatile("cp.async.commit_group;" ::: "memory"); }
__device__ __forceinline__ void cpa_wait0(){ asm volatile("cp.async.wait_group 0;" ::: "memory"); }

// ---------------- prep kernels ----------------
__global__ void prep_w1(const float* __restrict__ W1, const float* __restrict__ b2,
                        const float* __restrict__ fw){
    int idx = blockIdx.x * blockDim.x + threadIdx.x;
    if (idx < N_BANDS * MLPD * EMB){
        int k = idx & 127, o = (idx >> 7) & 511, n = idx >> 16;
        g_W1T[idx] = __float2half(W1[((size_t)n * EMB + k) * MLPD + o]);
    }
    if (idx < N_BANDS * W2ROWS){
        int r = idx % W2ROWS, n = idx / W2ROWS;
        int j = r >> 1, gbit = r & 1;
        float v = b2[(size_t)n * W2ROWS + (gbit ? j + 516 : j)];
        if (!gbit){
            int cc = j >= 258; int rem = j - cc * 258;
            v *= fw[n * BW_ + (rem >> 1)];
        }
        g_b2i[idx] = v;
    }
}
__global__ void prep_w2(const float* __restrict__ W2, const float* __restrict__ fw){
    int idx = blockIdx.x * blockDim.x + threadIdx.x;
    if (idx >= N_BANDS * W2PAD * MLPD) return;
    int k = idx & 511;
    int r = (idx >> 9) % W2PAD;
    int n = idx / (W2PAD * MLPD);
    float v = 0.0f;
    if (r < W2ROWS){
        int j = r >> 1, gbit = r & 1;
        int src_o = gbit ? j + 516 : j;
        v = W2[((size_t)n * MLPD + k) * W2ROWS + src_o];
        if (!gbit){
            int cc = j >= 258; int rem = j - cc * 258;
            v *= fw[n * BW_ + (rem >> 1)];
        }
    }
    g_W2T[(size_t)n * W2PAD * MLPD + (size_t)r * MLPD + k] = __float2half(v);
}

// ---------------- gather: sum overlapping bands -> final out ----------------
__global__ void gather_kernel(float* __restrict__ out, int B){
    int idx = blockIdx.x * blockDim.x + threadIdx.x;
    int total = B * 2 * NFREQ * TLEN;
    if (idx >= total) return;
    int t    = idx & (TLEN - 1);
    int rest = idx >> 11;
    int freq = rest % NFREQ;
    int rest2 = rest / NFREQ;
    int c = rest2 & 1;
    int b = rest2 >> 1;
    int n_lo = (freq >= 128) ? ((freq - 128 + 63) >> 6) : 0;
    int n_hi = freq >> 6; if (n_hi > 14) n_hi = 14;
    float s0 = 0.f, s1 = 0.f;
    for (int n = n_lo; n <= n_hi; n++){
        int f = freq - (n << 6);
        const float* base = g_scr + (((size_t)(b * N_BANDS + n) * 516) + (size_t)(c * 258 + 2 * f)) * TLEN + t;
        s0 += base[0];
        s1 += base[TLEN];
    }
    float2 v; v.x = s0; v.y = s1;
    ((float2*)out)[idx] = v;
}

// ---------------- main kernel ----------------
__global__ __launch_bounds__(NTH)
void omem_hmma_kernel(const float* __restrict__ q,
                      const float* __restrict__ ln_gamma,
                      const float* __restrict__ ln_beta,
                      const float* __restrict__ b1){
    extern __shared__ __align__(1024) char smem[];
    const uint32_t sb = smem_u32(smem);
    const int tid = threadIdx.x, warp = tid >> 5, lane = tid & 31;
    const int wm = warp & 7, whi = warp >> 3;   // GEMM1: whi=N-group; GEMM2: whi=K-half
    const int b = blockIdx.z, n = blockIdx.y, t0 = blockIdx.x * TMK;

    // ---- LayerNorm -> qn fp16, swizzled [128][256B] ----
    {
        const float* qb = q + ((size_t)(b * N_BANDS + n) * TLEN + t0) * EMB;
        float4 gg  = ((const float4*)(ln_gamma + (size_t)n * EMB))[lane];
        float4 bet = ((const float4*)(ln_beta  + (size_t)n * EMB))[lane];
        for (int i = warp; i < TMK; i += 16){
            float4 v = ((const float4*)(qb + (size_t)i * EMB))[lane];
            float s  = v.x + v.y + v.z + v.w;
            float s2 = v.x*v.x + v.y*v.y + v.z*v.z + v.w*v.w;
            #pragma unroll
            for (int off = 16; off; off >>= 1){
                s  += __shfl_xor_sync(0xffffffffu, s,  off);
                s2 += __shfl_xor_sync(0xffffffffu, s2, off);
            }
            float mu = s * (1.0f/EMB);
            float var = s2 * (1.0f/EMB) - mu*mu;
            float rs = rsqrtf(var + 1e-5f);
            uint2 pk;
            pk.x = f2h2((v.x - mu)*rs*gg.x + bet.x, (v.y - mu)*rs*gg.y + bet.y);
            pk.y = f2h2((v.z - mu)*rs*gg.z + bet.z, (v.w - mu)*rs*gg.w + bet.w);
            uint32_t ch = (uint32_t)(lane >> 1) ^ (uint32_t)(i & 7);
            *(uint2*)(smem + AQN_OFF + i * 256 + ch * 16 + (lane & 1) * 8) = pk;
        }
    }

    const uint32_t aRow = wm * 16 + (lane & 15);
    const uint32_t aS   = aRow & 7;
    const uint32_t aHi  = lane >> 4;
    const uint32_t bRowL = (lane & 7) | ((lane & 16) >> 1);
    const uint32_t bHi   = (lane >> 3) & 1;
    const uint32_t bS    = bRowL & 7;

    __syncthreads();

    // ---- GEMM1: z = qn @ W1T^T (M=128,K=128,N=512), 16 chunks of 32 rows ----
    {
        const __half* W1Tn = g_W1T + (size_t)n * MLPD * EMB;
        const float*  b1n  = b1 + (size_t)n * MLPD;
        const uint32_t aBase = sb + AQN_OFF + aRow * 256;
        {
            int r = tid >> 4, cn = tid & 15;
            cpa16(sb + STG_OFF + r * 256 + (((uint32_t)cn ^ (r & 7)) << 4),
                  W1Tn + (size_t)r * EMB + cn * 8);
            cpa_commit();
            cpa_wait0();
        }
        __syncthreads();
        #pragma unroll 1
        for (int c = 0; c < 16; c++){
            const int cbuf = c & 1, nbuf = (c + 1) & 1;
            if (c + 1 < 16){
                int r = tid >> 4, cn = tid & 15;
                cpa16(sb + STG_OFF + nbuf * 8192 + r * 256 + (((uint32_t)cn ^ (r & 7)) << 4),
                      W1Tn + (size_t)(c + 1) * 32 * EMB + (size_t)r * EMB + cn * 8);
                cpa_commit();
            }
            float acc[2][4];
            #pragma unroll
            for (int t = 0; t < 2; t++){ acc[t][0]=0.f; acc[t][1]=0.f; acc[t][2]=0.f; acc[t][3]=0.f; }
            const uint32_t sB = sb + STG_OFF + cbuf * 8192 + (whi * 16 + bRowL) * 256;
            #pragma unroll
            for (int ks = 0; ks < 8; ks++){
                uint32_t a[4], br[4];
                ldsm4(a,  aBase + ((((2*ks) + aHi) ^ aS) << 4));
                ldsm4(br, sB    + ((((2*ks) + bHi) ^ bS) << 4));
                mma16816(acc[0], a, br[0], br[1]);
                mma16816(acc[1], a, br[2], br[3]);
            }
            const uint32_t hr0 = wm * 16 + (lane >> 2);
            const uint32_t hr1 = hr0 + 8;
            #pragma unroll
            for (int t = 0; t < 2; t++){
                int ng = c * 32 + whi * 16 + t * 8 + 2 * (lane & 3);
                float2 bb = *(const float2*)(b1n + ng);
                uint32_t p0 = f2h2(tanhf(acc[t][0] + bb.x), tanhf(acc[t][1] + bb.y));
                uint32_t p1 = f2h2(tanhf(acc[t][2] + bb.x), tanhf(acc[t][3] + bb.y));
                uint32_t nbyte = (uint32_t)ng * 2u;
                uint32_t ch = nbyte >> 4, sub = nbyte & 15;
                *(uint32_t*)(smem + AH_OFF + hr0 * 1024 + ((ch ^ (hr0 & 7)) << 4) + sub) = p0;
                *(uint32_t*)(smem + AH_OFF + hr1 * 1024 + ((ch ^ (hr1 & 7)) << 4) + sub) = p1;
            }
            if (c + 1 < 16) cpa_wait0();
            __syncthreads();
        }
    }

    // ---- GEMM2: o = h @ W2T^T (M=128,K=512,Npad=1056), K-split across whi ----
    {
        const __half* W2Tn = g_W2T + (size_t)n * W2PAD * MLPD;
        const float*  b2in = g_b2i + n * W2ROWS;
        const uint32_t aBase = sb + AH_OFF + aRow * 1024;

        // A fragments for this warp's M=16 x K=256 slice, cached in registers
        uint32_t afr[16][4];
        #pragma unroll
        for (int ks = 0; ks < 16; ks++){
            int kk = whi * 16 + ks;
            ldsm4(afr[ks], aBase + ((((2*kk) + aHi) ^ aS) << 4));
        }

        // preload chunk 0 (32KB)
        {
            #pragma unroll
            for (int i = 0; i < 4; i++){
                int lin = i * NTH + tid; int r = lin >> 6, cn = lin & 63;
                cpa16(sb + STG_OFF + r * 1024 + (((uint32_t)cn ^ (r & 7)) << 4),
                      W2Tn + (size_t)r * MLPD + cn * 8);
            }
            cpa_commit();
            cpa_wait0();
        }
        __syncthreads();

        const size_t scrb = (size_t)(b * N_BANDS + n) * 516;
        const int tok0 = t0 + wm * 16 + (lane >> 2);

        #pragma unroll 1
        for (int c = 0; c < NCH2; c++){
            const int cbuf = c & 1, nbuf = (c + 1) & 1;
            if (c + 1 < NCH2){
                const __half* src = W2Tn + (size_t)(c + 1) * 32 * MLPD;
                #pragma unroll
                for (int i = 0; i < 4; i++){
                    int lin = i * NTH + tid; int r = lin >> 6, cn = lin & 63;
                    cpa16(sb + STG_OFF + nbuf * 32768 + r * 1024 + (((uint32_t)cn ^ (r & 7)) << 4),
                          src + (size_t)r * MLPD + cn * 8);
                }
                cpa_commit();
            }
            float acc[4][4];
            #pragma unroll
            for (int t = 0; t < 4; t++){ acc[t][0]=0.f; acc[t][1]=0.f; acc[t][2]=0.f; acc[t][3]=0.f; }
            const uint32_t sB0 = sb + STG_OFF + cbuf * 32768 + bRowL * 1024;
            const uint32_t sB1 = sB0 + 16 * 1024;
            #pragma unroll
            for (int ks = 0; ks < 16; ks++){
                int kk = whi * 16 + ks;
                uint32_t br0[4], br1[4];
                ldsm4(br0, sB0 + ((((2*kk) + bHi) ^ bS) << 4));
                ldsm4(br1, sB1 + ((((2*kk) + bHi) ^ bS) << 4));
                mma16816(acc[0], afr[ks], br0[0], br0[1]);
                mma16816(acc[1], afr[ks], br0[2], br0[3]);
                mma16816(acc[2], afr[ks], br1[0], br1[1]);
                mma16816(acc[3], afr[ks], br1[2], br1[3]);
            }
            // K-combine: each half owns 2 n-tiles, exchanges the other 2 via smem
            // comb[buf][slotFromKg][wm][i(0..7)][lane] : 2*2*8*8*32*4 = 32768B at AQN_OFF
            {
                const uint32_t cB = AQN_OFF + (uint32_t)(c & 1) * 16384u;
                // store non-owned tiles: whi==0 stores t2,t3 to slot0; whi==1 stores t0,t1 to slot1
                const uint32_t stSlot = cB + (uint32_t)whi * 8192u + (uint32_t)wm * 1024u + (uint32_t)lane * 4u;
                const int tSt = whi ? 0 : 2;
                #pragma unroll
                for (int i = 0; i < 8; i++){
                    *(float*)(smem + stSlot + i * 128) = acc[tSt + (i >> 2)][i & 3];
                }
                cpa_wait0();
                __syncthreads();
                // load the other half's contribution for owned tiles
                const uint32_t ldSlot = cB + (uint32_t)(whi ^ 1) * 8192u + (uint32_t)wm * 1024u + (uint32_t)lane * 4u;
                const int tOwn = whi ? 2 : 0;
                float ss[8];
                #pragma unroll
                for (int i = 0; i < 8; i++) ss[i] = *(const float*)(smem + ldSlot + i * 128);
                // epilogue for owned tiles
                #pragma unroll
                for (int t = 0; t < 2; t++){
                    int tt = tOwn + t;
                    int jp = c * 16 + tt * 4 + (lane & 3);
                    if (jp < 516){
                        float2 bb = *(const float2*)(b2in + 2 * jp);
                        float a0 = acc[tt][0] + ss[t*4+0] + bb.x;
                        float g0 = acc[tt][1] + ss[t*4+1] + bb.y;
                        float a1 = acc[tt][2] + ss[t*4+2] + bb.x;
                        float g1 = acc[tt][3] + ss[t*4+3] + bb.y;
                        float* dst = g_scr + (scrb + (size_t)jp) * TLEN + tok0;
                        dst[0] = a0 / (1.0f + __expf(-g0));
                        dst[8] = a1 / (1.0f + __expf(-g1));
                    }
                }
            }
        }
    }
}

extern "C" void kernel_launch(void* const* d_in, const int* in_sizes, int n_in,
                              void* d_out, int out_size){
    const float* q        = (const float*)d_in[0];
    const float* ln_gamma = (const float*)d_in[1];
    const float* ln_beta  = (const float*)d_in[2];
    const float* W1       = (const float*)d_in[3];
    const float* b1       = (const float*)d_in[4];
    const float* W2       = (const float*)d_in[5];
    const float* b2       = (const float*)d_in[6];
    const float* fw       = (const float*)d_in[7];
    float* out = (float*)d_out;

    int B = in_sizes[0] / (N_BANDS * TLEN * EMB);

    {
        int tot1 = N_BANDS * MLPD * EMB;
        prep_w1<<<(tot1 + 255) / 256, 256>>>(W1, b2, fw);
        int tot2 = N_BANDS * W2PAD * MLPD;
        prep_w2<<<(tot2 + 255) / 256, 256>>>(W2, fw);
    }
    cudaFuncSetAttribute(omem_hmma_kernel, cudaFuncAttributeMaxDynamicSharedMemorySize, SMEM_TOTAL);
    dim3 grid(TLEN / TMK, N_BANDS, B);
    omem_hmma_kernel<<<grid, NTH, SMEM_TOTAL>>>(q, ln_gamma, ln_beta, b1);

    {
        int total = B * 2 * NFREQ * TLEN;
        gather_kernel<<<(total + 255) / 256, 256>>>(out, B);
    }
}

// round 8
// speedup vs baseline: 8.2151x; 1.0688x over previous
#include <cuda_runtime.h>
#include <cuda_fp16.h>
#include <stdint.h>
#include <math.h>

#define N_BANDS 15
#define BW_     129
#define HOP_    64
#define NFREQ   1025
#define EMB     128
#define MLPD    512
#define TLEN    2048
#define TM      64
#define NTH     256
#define W2ROWS  1032
#define W2PAD   1056
#define NCH2    33

// smem layout (bytes) — 96KB total -> 2 CTAs/SM
#define AH_OFF    0          // h fp16 [64][1024B] swizzled = 65536
#define AQN_OFF   65536      // GEMM1: qn [64][256B] = 16384
#define W1STG_OFF 81920      // GEMM1: 2 x 8192
#define W2STG_OFF 65536      // GEMM2: single 32768 buffer (aliases qn+W1 stg)
#define SMEM_TOTAL 98304

__device__ __align__(16) __half g_W1T[(size_t)N_BANDS * MLPD * EMB];
__device__ __align__(16) __half g_W2T[(size_t)N_BANDS * W2PAD * MLPD];
__device__ float g_b2i[N_BANDS * W2ROWS];
__device__ float g_scr[(size_t)2 * N_BANDS * 516 * TLEN];   // [b][n][pair][t]

__device__ __forceinline__ uint32_t smem_u32(const void* p){
    uint32_t a;
    asm("{ .reg .u64 t; cvta.to.shared.u64 t, %1; cvt.u32.u64 %0, t; }" : "=r"(a) : "l"(p));
    return a;
}
__device__ __forceinline__ void ldsm4(uint32_t* r, uint32_t a){
    asm volatile("ldmatrix.sync.aligned.m8n8.x4.shared.b16 {%0,%1,%2,%3}, [%4];"
        : "=r"(r[0]),"=r"(r[1]),"=r"(r[2]),"=r"(r[3]) : "r"(a));
}
__device__ __forceinline__ void mma16816(float* c, const uint32_t* a, uint32_t b0, uint32_t b1){
    asm volatile("mma.sync.aligned.m16n8k16.row.col.f32.f16.f16.f32 "
        "{%0,%1,%2,%3}, {%4,%5,%6,%7}, {%8,%9}, {%0,%1,%2,%3};"
        : "+f"(c[0]),"+f"(c[1]),"+f"(c[2]),"+f"(c[3])
        : "r"(a[0]),"r"(a[1]),"r"(a[2]),"r"(a[3]),"r"(b0),"r"(b1));
}
__device__ __forceinline__ uint32_t f2h2(float a, float b){
    __half2 h = __floats2half2_rn(a, b);
    return *(uint32_t*)&h;
}
__device__ __forceinline__ void cpa16(uint32_t dst, const void* src){
    asm volatile("cp.async.ca.shared.global [%0], [%1], 16;" :: "r"(dst), "l"(src));
}
__device__ __forceinline__ void cpa_commit(){ asm volatile("cp.async.commit_group;" ::: "memory"); }
__device__ __forceinline__ void cpa_wait0(){ asm volatile("cp.async.wait_group 0;" ::: "memory"); }

// ---------------- prep kernels ----------------
__global__ void prep_w1(const float* __restrict__ W1, const float* __restrict__ b2,
                        const float* __restrict__ fw){
    int idx = blockIdx.x * blockDim.x + threadIdx.x;
    if (idx < N_BANDS * MLPD * EMB){
        int k = idx & 127, o = (idx >> 7) & 511, n = idx >> 16;
        g_W1T[idx] = __float2half(W1[((size_t)n * EMB + k) * MLPD + o]);
    }
    if (idx < N_BANDS * W2ROWS){
        int r = idx % W2ROWS, n = idx / W2ROWS;
        int j = r >> 1, gbit = r & 1;
        float v = b2[(size_t)n * W2ROWS + (gbit ? j + 516 : j)];
        if (!gbit){
            int cc = j >= 258; int rem = j - cc * 258;
            v *= fw[n * BW_ + (rem >> 1)];
        }
        g_b2i[idx] = v;
    }
}
__global__ void prep_w2(const float* __restrict__ W2, const float* __restrict__ fw){
    int idx = blockIdx.x * blockDim.x + threadIdx.x;
    if (idx >= N_BANDS * W2PAD * MLPD) return;
    int k = idx & 511;
    int r = (idx >> 9) % W2PAD;
    int n = idx / (W2PAD * MLPD);
    float v = 0.0f;
    if (r < W2ROWS){
        int j = r >> 1, gbit = r & 1;
        int src_o = gbit ? j + 516 : j;
        v = W2[((size_t)n * MLPD + k) * W2ROWS + src_o];
        if (!gbit){
            int cc = j >= 258; int rem = j - cc * 258;
            v *= fw[n * BW_ + (rem >> 1)];
        }
    }
    g_W2T[(size_t)n * W2PAD * MLPD + (size_t)r * MLPD + k] = __float2half(v);
}

// ---------------- gather: sum overlapping bands -> final out ----------------
__global__ void gather_kernel(float* __restrict__ out, int B){
    int idx = blockIdx.x * blockDim.x + threadIdx.x;
    int total = B * 2 * NFREQ * TLEN;
    if (idx >= total) return;
    int t    = idx & (TLEN - 1);
    int rest = idx >> 11;
    int freq = rest % NFREQ;
    int rest2 = rest / NFREQ;
    int c = rest2 & 1;
    int b = rest2 >> 1;
    int n_lo = (freq >= 128) ? ((freq - 128 + 63) >> 6) : 0;
    int n_hi = freq >> 6; if (n_hi > 14) n_hi = 14;
    float s0 = 0.f, s1 = 0.f;
    for (int n = n_lo; n <= n_hi; n++){
        int f = freq - (n << 6);
        const float* base = g_scr + (((size_t)(b * N_BANDS + n) * 516) + (size_t)(c * 258 + 2 * f)) * TLEN + t;
        s0 += base[0];
        s1 += base[TLEN];
    }
    float2 v; v.x = s0; v.y = s1;
    ((float2*)out)[idx] = v;
}

// ---------------- main kernel ----------------
__global__ __launch_bounds__(NTH, 2)
void omem_hmma_kernel(const float* __restrict__ q,
                      const float* __restrict__ ln_gamma,
                      const float* __restrict__ ln_beta,
                      const float* __restrict__ b1){
    extern __shared__ __align__(1024) char smem[];
    const uint32_t sb = smem_u32(smem);
    const int tid = threadIdx.x, warp = tid >> 5, lane = tid & 31;
    const int wm = warp & 3, wn = warp >> 2;   // 4 M-warps x 2 N-groups
    const int b = blockIdx.z, n = blockIdx.y, t0 = blockIdx.x * TM;

    // ---- LayerNorm -> qn fp16, swizzled [64][256B] ----
    {
        const float* qb = q + ((size_t)(b * N_BANDS + n) * TLEN + t0) * EMB;
        float4 gg  = ((const float4*)(ln_gamma + (size_t)n * EMB))[lane];
        float4 bet = ((const float4*)(ln_beta  + (size_t)n * EMB))[lane];
        for (int i = warp; i < TM; i += 8){
            float4 v = ((const float4*)(qb + (size_t)i * EMB))[lane];
            float s  = v.x + v.y + v.z + v.w;
            float s2 = v.x*v.x + v.y*v.y + v.z*v.z + v.w*v.w;
            #pragma unroll
            for (int off = 16; off; off >>= 1){
                s  += __shfl_xor_sync(0xffffffffu, s,  off);
                s2 += __shfl_xor_sync(0xffffffffu, s2, off);
            }
            float mu = s * (1.0f/EMB);
            float var = s2 * (1.0f/EMB) - mu*mu;
            float rs = rsqrtf(var + 1e-5f);
            uint2 pk;
            pk.x = f2h2((v.x - mu)*rs*gg.x + bet.x, (v.y - mu)*rs*gg.y + bet.y);
            pk.y = f2h2((v.z - mu)*rs*gg.z + bet.z, (v.w - mu)*rs*gg.w + bet.w);
            uint32_t ch = (uint32_t)(lane >> 1) ^ (uint32_t)(i & 7);
            *(uint2*)(smem + AQN_OFF + i * 256 + ch * 16 + (lane & 1) * 8) = pk;
        }
    }

    const uint32_t aRow = wm * 16 + (lane & 15);
    const uint32_t aS   = aRow & 7;
    const uint32_t aHi  = lane >> 4;
    const uint32_t bRowL = (lane & 7) | ((lane & 16) >> 1);
    const uint32_t bHi   = (lane >> 3) & 1;
    const uint32_t bS    = bRowL & 7;

    __syncthreads();

    // ---- GEMM1: z = qn @ W1T^T (M=64,K=128,N=512), 16 chunks of 32 rows ----
    {
        const __half* W1Tn = g_W1T + (size_t)n * MLPD * EMB;
        const float*  b1n  = b1 + (size_t)n * MLPD;
        const uint32_t aBase = sb + AQN_OFF + aRow * 256;
        // preload chunk 0 into buf 0 (8KB = 2 cpa16/thread)
        {
            #pragma unroll
            for (int i = 0; i < 2; i++){
                int lin = i * NTH + tid; int r = lin >> 4, cn = lin & 15;
                cpa16(sb + W1STG_OFF + r * 256 + (((uint32_t)cn ^ (r & 7)) << 4),
                      W1Tn + (size_t)r * EMB + cn * 8);
            }
            cpa_commit();
            cpa_wait0();
        }
        __syncthreads();
        #pragma unroll 1
        for (int c = 0; c < 16; c++){
            const int cbuf = c & 1, nbuf = (c + 1) & 1;
            if (c + 1 < 16){
                #pragma unroll
                for (int i = 0; i < 2; i++){
                    int lin = i * NTH + tid; int r = lin >> 4, cn = lin & 15;
                    cpa16(sb + W1STG_OFF + nbuf * 8192 + r * 256 + (((uint32_t)cn ^ (r & 7)) << 4),
                          W1Tn + (size_t)(c + 1) * 32 * EMB + (size_t)r * EMB + cn * 8);
                }
                cpa_commit();
            }
            float acc[2][4];
            #pragma unroll
            for (int t = 0; t < 2; t++){ acc[t][0]=0.f; acc[t][1]=0.f; acc[t][2]=0.f; acc[t][3]=0.f; }
            const uint32_t sB = sb + W1STG_OFF + cbuf * 8192 + (wn * 16 + bRowL) * 256;
            #pragma unroll
            for (int ks = 0; ks < 8; ks++){
                uint32_t a[4], br[4];
                ldsm4(a,  aBase + ((((2*ks) + aHi) ^ aS) << 4));
                ldsm4(br, sB    + ((((2*ks) + bHi) ^ bS) << 4));
                mma16816(acc[0], a, br[0], br[1]);
                mma16816(acc[1], a, br[2], br[3]);
            }
            const uint32_t hr0 = wm * 16 + (lane >> 2);
            const uint32_t hr1 = hr0 + 8;
            #pragma unroll
            for (int t = 0; t < 2; t++){
                int ng = c * 32 + wn * 16 + t * 8 + 2 * (lane & 3);
                float2 bb = *(const float2*)(b1n + ng);
                uint32_t p0 = f2h2(tanhf(acc[t][0] + bb.x), tanhf(acc[t][1] + bb.y));
                uint32_t p1 = f2h2(tanhf(acc[t][2] + bb.x), tanhf(acc[t][3] + bb.y));
                uint32_t nbyte = (uint32_t)ng * 2u;
                uint32_t ch = nbyte >> 4, sub = nbyte & 15;
                *(uint32_t*)(smem + AH_OFF + hr0 * 1024 + ((ch ^ (hr0 & 7)) << 4) + sub) = p0;
                *(uint32_t*)(smem + AH_OFF + hr1 * 1024 + ((ch ^ (hr1 & 7)) << 4) + sub) = p1;
            }
            if (c + 1 < 16) cpa_wait0();
            __syncthreads();
        }
    }

    // ---- GEMM2: o = h @ W2T^T (M=64,K=512,Npad=1056), 33 chunks, single buffer ----
    {
        const __half* W2Tn = g_W2T + (size_t)n * W2PAD * MLPD;
        const float*  b2in = g_b2i + n * W2ROWS;
        const uint32_t aBase = sb + AH_OFF + aRow * 1024;

        // preload chunk 0 (32KB = 8 cpa16/thread); also acts as barrier before
        // W2 staging overwrites the (dead) qn/W1 region.
        {
            #pragma unroll
            for (int i = 0; i < 8; i++){
                int lin = i * NTH + tid; int r = lin >> 6, cn = lin & 63;
                cpa16(sb + W2STG_OFF + r * 1024 + (((uint32_t)cn ^ (r & 7)) << 4),
                      W2Tn + (size_t)r * MLPD + cn * 8);
            }
            cpa_commit();
            cpa_wait0();
        }
        __syncthreads();

        const size_t scrb = (size_t)(b * N_BANDS + n) * 516;
        const int tok0 = t0 + wm * 16 + (lane >> 2);

        #pragma unroll 1
        for (int c = 0; c < NCH2; c++){
            float acc[2][4];
            #pragma unroll
            for (int t = 0; t < 2; t++){ acc[t][0]=0.f; acc[t][1]=0.f; acc[t][2]=0.f; acc[t][3]=0.f; }
            const uint32_t sB = sb + W2STG_OFF + (wn * 16 + bRowL) * 1024;
            #pragma unroll 8
            for (int ks = 0; ks < 32; ks++){
                uint32_t a[4], br[4];
                ldsm4(a,  aBase + ((((2*ks) + aHi) ^ aS) << 4));
                ldsm4(br, sB    + ((((2*ks) + bHi) ^ bS) << 4));
                mma16816(acc[0], a, br[0], br[1]);
                mma16816(acc[1], a, br[2], br[3]);
            }
            __syncthreads();   // all warps done reading this chunk's buffer
            if (c + 1 < NCH2){
                const __half* src = W2Tn + (size_t)(c + 1) * 32 * MLPD;
                #pragma unroll
                for (int i = 0; i < 8; i++){
                    int lin = i * NTH + tid; int r = lin >> 6, cn = lin & 63;
                    cpa16(sb + W2STG_OFF + r * 1024 + (((uint32_t)cn ^ (r & 7)) << 4),
                          src + (size_t)r * MLPD + cn * 8);
                }
                cpa_commit();
            }
            // epilogue overlaps the async load (touches no smem)
            #pragma unroll
            for (int t = 0; t < 2; t++){
                int jp = c * 16 + wn * 8 + t * 4 + (lane & 3);
                if (jp < 516){
                    float2 bb = *(const float2*)(b2in + 2 * jp);
                    float a0 = acc[t][0] + bb.x, g0 = acc[t][1] + bb.y;
                    float a1 = acc[t][2] + bb.x, g1 = acc[t][3] + bb.y;
                    float* dst = g_scr + (scrb + (size_t)jp) * TLEN + tok0;
                    dst[0] = a0 / (1.0f + __expf(-g0));
                    dst[8] = a1 / (1.0f + __expf(-g1));
                }
            }
            if (c + 1 < NCH2) cpa_wait0();
            __syncthreads();
        }
    }
}

extern "C" void kernel_launch(void* const* d_in, const int* in_sizes, int n_in,
                              void* d_out, int out_size){
    const float* q        = (const float*)d_in[0];
    const float* ln_gamma = (const float*)d_in[1];
    const float* ln_beta  = (const float*)d_in[2];
    const float* W1       = (const float*)d_in[3];
    const float* b1       = (const float*)d_in[4];
    const float* W2       = (const float*)d_in[5];
    const float* b2       = (const float*)d_in[6];
    const float* fw       = (const float*)d_in[7];
    float* out = (float*)d_out;

    int B = in_sizes[0] / (N_BANDS * TLEN * EMB);

    {
        int tot1 = N_BANDS * MLPD * EMB;
        prep_w1<<<(tot1 + 255) / 256, 256>>>(W1, b2, fw);
        int tot2 = N_BANDS * W2PAD * MLPD;
        prep_w2<<<(tot2 + 255) / 256, 256>>>(W2, fw);
    }
    cudaFuncSetAttribute(omem_hmma_kernel, cudaFuncAttributeMaxDynamicSharedMemorySize, SMEM_TOTAL);
    dim3 grid(TLEN / TM, N_BANDS, B);
    omem_hmma_kernel<<<grid, NTH, SMEM_TOTAL>>>(q, ln_gamma, ln_beta, b1);

    {
        int total = B * 2 * NFREQ * TLEN;
        gather_kernel<<<(total + 255) / 256, 256>>>(out, B);
    }
}

// round 9
// speedup vs baseline: 8.6522x; 1.0532x over previous
#include <cuda_runtime.h>
#include <cuda_fp16.h>
#include <stdint.h>
#include <math.h>

#define N_BANDS 15
#define BW_     129
#define HOP_    64
#define NFREQ   1025
#define EMB     128
#define MLPD    512
#define TLEN    2048
#define TM      64
#define NTH     256
#define W2ROWS  1032
#define W2PAD   1056
#define NCH2    33

// smem layout (bytes) — 96KB total -> 2 CTAs/SM
#define AH_OFF    0
#define AQN_OFF   65536
#define W1STG_OFF 81920
#define W2STG_OFF 65536
#define SMEM_TOTAL 98304

__device__ __align__(16) __half g_W1T[(size_t)N_BANDS * MLPD * EMB];
__device__ __align__(16) __half g_W2T[(size_t)N_BANDS * W2PAD * MLPD];
__device__ float g_b2i[N_BANDS * W2ROWS];
__device__ float g_scr[(size_t)2 * N_BANDS * 516 * TLEN];

__device__ __forceinline__ uint32_t smem_u32(const void* p){
    uint32_t a;
    asm("{ .reg .u64 t; cvta.to.shared.u64 t, %1; cvt.u32.u64 %0, t; }" : "=r"(a) : "l"(p));
    return a;
}
__device__ __forceinline__ void ldsm4(uint32_t* r, uint32_t a){
    asm volatile("ldmatrix.sync.aligned.m8n8.x4.shared.b16 {%0,%1,%2,%3}, [%4];"
        : "=r"(r[0]),"=r"(r[1]),"=r"(r[2]),"=r"(r[3]) : "r"(a));
}
__device__ __forceinline__ void mma16816(float* c, const uint32_t* a, uint32_t b0, uint32_t b1){
    asm volatile("mma.sync.aligned.m16n8k16.row.col.f32.f16.f16.f32 "
        "{%0,%1,%2,%3}, {%4,%5,%6,%7}, {%8,%9}, {%0,%1,%2,%3};"
        : "+f"(c[0]),"+f"(c[1]),"+f"(c[2]),"+f"(c[3])
        : "r"(a[0]),"r"(a[1]),"r"(a[2]),"r"(a[3]),"r"(b0),"r"(b1));
}
__device__ __forceinline__ uint32_t f2h2(float a, float b){
    __half2 h = __floats2half2_rn(a, b);
    return *(uint32_t*)&h;
}
__device__ __forceinline__ void cpa16(uint32_t dst, const void* src){
    asm volatile("cp.async.ca.shared.global [%0], [%1], 16;" :: "r"(dst), "l"(src));
}
__device__ __forceinline__ void cpa_commit(){ asm volatile("cp.async.commit_group;" ::: "memory"); }
__device__ __forceinline__ void cpa_wait0(){ asm volatile("cp.async.wait_group 0;" ::: "memory"); }

__device__ __forceinline__ float tanh_fast(float x){
    x = fminf(fmaxf(x, -15.f), 15.f);
    float e = __expf(2.0f * x);
    return __fdividef(e - 1.0f, e + 1.0f);
}
__device__ __forceinline__ float sigm_fast(float g){
    return __fdividef(1.0f, 1.0f + __expf(-g));
}

// ---------------- prep kernels (tiled transposes, coalesced) ----------------
__global__ void prep_b2i(const float* __restrict__ b2, const float* __restrict__ fw){
    int idx = blockIdx.x * blockDim.x + threadIdx.x;
    if (idx >= N_BANDS * W2ROWS) return;
    int r = idx % W2ROWS, n = idx / W2ROWS;
    int j = r >> 1, gbit = r & 1;
    float v = b2[(size_t)n * W2ROWS + (gbit ? j + 516 : j)];
    if (!gbit){
        int cc = j >= 258; int rem = j - cc * 258;
        v *= fw[n * BW_ + (rem >> 1)];
    }
    g_b2i[idx] = v;
}

__global__ void prep_w1_t(const float* __restrict__ W1){
    __shared__ float s[64][65];
    const int n = blockIdx.z, f0 = blockIdx.y * 64, e0 = blockIdx.x * 64;
    const int tid = threadIdx.x;
    const int i0 = tid >> 6, j = tid & 63;
    const float* src = W1 + ((size_t)n * EMB + e0) * MLPD + f0;
    #pragma unroll
    for (int p = 0; p < 16; p++){
        int i = p * 4 + i0;
        s[i][j] = src[(size_t)i * MLPD + j];
    }
    __syncthreads();
    __half* dst = g_W1T + ((size_t)n * MLPD + f0) * EMB + e0;
    #pragma unroll
    for (int p = 0; p < 16; p++){
        int jj = p * 4 + i0;
        dst[(size_t)jj * EMB + j] = __float2half(s[j][jj]);
    }
}

__global__ void prep_w2_t(const float* __restrict__ W2, const float* __restrict__ fw){
    __shared__ float sa[64][33], sg[64][33];
    const int n = blockIdx.z, j0 = blockIdx.y * 32, k0 = blockIdx.x * 64;
    const int tid = threadIdx.x;
    const int kk0 = tid >> 5, jj = tid & 31;
    const float* src = W2 + (size_t)n * MLPD * W2ROWS + (size_t)k0 * W2ROWS;
    const int jf_l = j0 + jj;
    #pragma unroll
    for (int p = 0; p < 8; p++){
        int kk = p * 8 + kk0;
        float va = 0.f, vg = 0.f;
        if (jf_l < 516){
            va = src[(size_t)kk * W2ROWS + jf_l];
            vg = src[(size_t)kk * W2ROWS + 516 + jf_l];
        }
        sa[kk][jj] = va; sg[kk][jj] = vg;
    }
    __syncthreads();
    const int w = tid >> 5, kk2 = tid & 31;
    #pragma unroll
    for (int p = 0; p < 8; p++){
        int rl = p * 8 + w;
        int jj2 = rl >> 1, g = rl & 1;
        int jf = j0 + jj2;
        int r = 2 * jf + g;
        if (r < W2PAD){
            float v0, v1;
            if (g){ v0 = sg[2*kk2][jj2]; v1 = sg[2*kk2+1][jj2]; }
            else {
                v0 = sa[2*kk2][jj2]; v1 = sa[2*kk2+1][jj2];
                if (jf < 516){
                    int cc = jf >= 258; int rem = jf - cc * 258;
                    float fwv = fw[n * BW_ + (rem >> 1)];
                    v0 *= fwv; v1 *= fwv;
                }
            }
            *(__half2*)(g_W2T + ((size_t)n * W2PAD + r) * MLPD + k0 + 2 * kk2) =
                __floats2half2_rn(v0, v1);
        }
    }
}

// ---------------- gather ----------------
__global__ void gather_kernel(float* __restrict__ out, int B){
    int idx = blockIdx.x * blockDim.x + threadIdx.x;
    int total = B * 2 * NFREQ * TLEN;
    if (idx >= total) return;
    int t    = idx & (TLEN - 1);
    int rest = idx >> 11;
    int freq = rest % NFREQ;
    int rest2 = rest / NFREQ;
    int c = rest2 & 1;
    int b = rest2 >> 1;
    int n_lo = (freq >= 128) ? ((freq - 128 + 63) >> 6) : 0;
    int n_hi = freq >> 6; if (n_hi > 14) n_hi = 14;
    float s0 = 0.f, s1 = 0.f;
    for (int n = n_lo; n <= n_hi; n++){
        int f = freq - (n << 6);
        const float* base = g_scr + (((size_t)(b * N_BANDS + n) * 516) + (size_t)(c * 258 + 2 * f)) * TLEN + t;
        s0 += base[0];
        s1 += base[TLEN];
    }
    float2 v; v.x = s0; v.y = s1;
    ((float2*)out)[idx] = v;
}

// ---------------- main kernel ----------------
__global__ __launch_bounds__(NTH, 2)
void omem_hmma_kernel(const float* __restrict__ q,
                      const float* __restrict__ ln_gamma,
                      const float* __restrict__ ln_beta,
                      const float* __restrict__ b1){
    extern __shared__ __align__(1024) char smem[];
    const uint32_t sb = smem_u32(smem);
    const int tid = threadIdx.x, warp = tid >> 5, lane = tid & 31;
    const int wm = warp & 3, wn = warp >> 2;
    const int b = blockIdx.z, n = blockIdx.y, t0 = blockIdx.x * TM;

    // ---- LayerNorm -> qn fp16, swizzled [64][256B] ----
    {
        const float* qb = q + ((size_t)(b * N_BANDS + n) * TLEN + t0) * EMB;
        float4 gg  = ((const float4*)(ln_gamma + (size_t)n * EMB))[lane];
        float4 bet = ((const float4*)(ln_beta  + (size_t)n * EMB))[lane];
        for (int i = warp; i < TM; i += 8){
            float4 v = ((const float4*)(qb + (size_t)i * EMB))[lane];
            float s  = v.x + v.y + v.z + v.w;
            float s2 = v.x*v.x + v.y*v.y + v.z*v.z + v.w*v.w;
            #pragma unroll
            for (int off = 16; off; off >>= 1){
                s  += __shfl_xor_sync(0xffffffffu, s,  off);
                s2 += __shfl_xor_sync(0xffffffffu, s2, off);
            }
            float mu = s * (1.0f/EMB);
            float var = s2 * (1.0f/EMB) - mu*mu;
            float rs = rsqrtf(var + 1e-5f);
            uint2 pk;
            pk.x = f2h2((v.x - mu)*rs*gg.x + bet.x, (v.y - mu)*rs*gg.y + bet.y);
            pk.y = f2h2((v.z - mu)*rs*gg.z + bet.z, (v.w - mu)*rs*gg.w + bet.w);
            uint32_t ch = (uint32_t)(lane >> 1) ^ (uint32_t)(i & 7);
            *(uint2*)(smem + AQN_OFF + i * 256 + ch * 16 + (lane & 1) * 8) = pk;
        }
    }

    const uint32_t aRow = wm * 16 + (lane & 15);
    const uint32_t aS   = aRow & 7;
    const uint32_t aHi  = lane >> 4;
    const uint32_t bRowL = (lane & 7) | ((lane & 16) >> 1);
    const uint32_t bHi   = (lane >> 3) & 1;
    const uint32_t bS    = bRowL & 7;

    // swizzle offsets, period 4 in ks: ((2j+hi)^s)<<4
    uint32_t aOff[4], bOff[4];
    #pragma unroll
    for (int j2 = 0; j2 < 4; j2++){
        aOff[j2] = (((2u*j2 + aHi) ^ aS) << 4);
        bOff[j2] = (((2u*j2 + bHi) ^ bS) << 4);
    }

    __syncthreads();

    // ---- GEMM1: z = qn @ W1T^T (M=64,K=128,N=512) ----
    {
        const __half* W1Tn = g_W1T + (size_t)n * MLPD * EMB;
        const float*  b1n  = b1 + (size_t)n * MLPD;
        uint32_t aA[4];
        #pragma unroll
        for (int j2 = 0; j2 < 4; j2++) aA[j2] = sb + AQN_OFF + aRow * 256 + aOff[j2];
        {
            #pragma unroll
            for (int i = 0; i < 2; i++){
                int lin = i * NTH + tid; int r = lin >> 4, cn = lin & 15;
                cpa16(sb + W1STG_OFF + r * 256 + (((uint32_t)cn ^ (r & 7)) << 4),
                      W1Tn + (size_t)r * EMB + cn * 8);
            }
            cpa_commit();
            cpa_wait0();
        }
        __syncthreads();
        #pragma unroll 1
        for (int c = 0; c < 16; c++){
            const int cbuf = c & 1, nbuf = (c + 1) & 1;
            if (c + 1 < 16){
                #pragma unroll
                for (int i = 0; i < 2; i++){
                    int lin = i * NTH + tid; int r = lin >> 4, cn = lin & 15;
                    cpa16(sb + W1STG_OFF + nbuf * 8192 + r * 256 + (((uint32_t)cn ^ (r & 7)) << 4),
                          W1Tn + (size_t)(c + 1) * 32 * EMB + (size_t)r * EMB + cn * 8);
                }
                cpa_commit();
            }
            float acc[2][4];
            #pragma unroll
            for (int t = 0; t < 2; t++){ acc[t][0]=0.f; acc[t][1]=0.f; acc[t][2]=0.f; acc[t][3]=0.f; }
            uint32_t bA[4];
            #pragma unroll
            for (int j2 = 0; j2 < 4; j2++)
                bA[j2] = sb + W1STG_OFF + cbuf * 8192 + (wn * 16 + bRowL) * 256 + bOff[j2];
            #pragma unroll
            for (int ks = 0; ks < 8; ks++){
                uint32_t a[4], br[4];
                uint32_t ko = (ks >> 2) * 128;
                ldsm4(a,  aA[ks & 3] + ko);
                ldsm4(br, bA[ks & 3] + ko);
                mma16816(acc[0], a, br[0], br[1]);
                mma16816(acc[1], a, br[2], br[3]);
            }
            const uint32_t hr0 = wm * 16 + (lane >> 2);
            const uint32_t hr1 = hr0 + 8;
            #pragma unroll
            for (int t = 0; t < 2; t++){
                int ng = c * 32 + wn * 16 + t * 8 + 2 * (lane & 3);
                float2 bb = *(const float2*)(b1n + ng);
                uint32_t p0 = f2h2(tanh_fast(acc[t][0] + bb.x), tanh_fast(acc[t][1] + bb.y));
                uint32_t p1 = f2h2(tanh_fast(acc[t][2] + bb.x), tanh_fast(acc[t][3] + bb.y));
                uint32_t nbyte = (uint32_t)ng * 2u;
                uint32_t ch = nbyte >> 4, sub = nbyte & 15;
                *(uint32_t*)(smem + AH_OFF + hr0 * 1024 + ((ch ^ (hr0 & 7)) << 4) + sub) = p0;
                *(uint32_t*)(smem + AH_OFF + hr1 * 1024 + ((ch ^ (hr1 & 7)) << 4) + sub) = p1;
            }
            if (c + 1 < 16) cpa_wait0();
            __syncthreads();
        }
    }

    // ---- GEMM2: o = h @ W2T^T (M=64,K=512,Npad=1056), single buffer ----
    {
        const __half* W2Tn = g_W2T + (size_t)n * W2PAD * MLPD;
        const float*  b2in = g_b2i + n * W2ROWS;
        uint32_t aA[4], bA[4];
        #pragma unroll
        for (int j2 = 0; j2 < 4; j2++){
            aA[j2] = sb + AH_OFF + aRow * 1024 + aOff[j2];
            bA[j2] = sb + W2STG_OFF + (wn * 16 + bRowL) * 1024 + bOff[j2];
        }
        {
            #pragma unroll
            for (int i = 0; i < 8; i++){
                int lin = i * NTH + tid; int r = lin >> 6, cn = lin & 63;
                cpa16(sb + W2STG_OFF + r * 1024 + (((uint32_t)cn ^ (r & 7)) << 4),
                      W2Tn + (size_t)r * MLPD + cn * 8);
            }
            cpa_commit();
            cpa_wait0();
        }
        __syncthreads();

        const size_t scrb = (size_t)(b * N_BANDS + n) * 516;
        const int tok0 = t0 + wm * 16 + (lane >> 2);

        #pragma unroll 1
        for (int c = 0; c < NCH2; c++){
            float acc[2][4];
            #pragma unroll
            for (int t = 0; t < 2; t++){ acc[t][0]=0.f; acc[t][1]=0.f; acc[t][2]=0.f; acc[t][3]=0.f; }
            #pragma unroll 8
            for (int ks = 0; ks < 32; ks++){
                uint32_t a[4], br[4];
                uint32_t ko = (ks >> 2) * 128;
                ldsm4(a,  aA[ks & 3] + ko);
                ldsm4(br, bA[ks & 3] + ko);
                mma16816(acc[0], a, br[0], br[1]);
                mma16816(acc[1], a, br[2], br[3]);
            }
            __syncthreads();
            if (c + 1 < NCH2){
                const __half* src = W2Tn + (size_t)(c + 1) * 32 * MLPD;
                #pragma unroll
                for (int i = 0; i < 8; i++){
                    int lin = i * NTH + tid; int r = lin >> 6, cn = lin & 63;
                    cpa16(sb + W2STG_OFF + r * 1024 + (((uint32_t)cn ^ (r & 7)) << 4),
                          src + (size_t)r * MLPD + cn * 8);
                }
                cpa_commit();
            }
            #pragma unroll
            for (int t = 0; t < 2; t++){
                int jp = c * 16 + wn * 8 + t * 4 + (lane & 3);
                if (jp < 516){
                    float2 bb = *(const float2*)(b2in + 2 * jp);
                    float a0 = acc[t][0] + bb.x, g0 = acc[t][1] + bb.y;
                    float a1 = acc[t][2] + bb.x, g1 = acc[t][3] + bb.y;
                    float* dst = g_scr + (scrb + (size_t)jp) * TLEN + tok0;
                    dst[0] = a0 * sigm_fast(g0);
                    dst[8] = a1 * sigm_fast(g1);
                }
            }
            if (c + 1 < NCH2) cpa_wait0();
            __syncthreads();
        }
    }
}

extern "C" void kernel_launch(void* const* d_in, const int* in_sizes, int n_in,
                              void* d_out, int out_size){
    const float* q        = (const float*)d_in[0];
    const float* ln_gamma = (const float*)d_in[1];
    const float* ln_beta  = (const float*)d_in[2];
    const float* W1       = (const float*)d_in[3];
    const float* b1       = (const float*)d_in[4];
    const float* W2       = (const float*)d_in[5];
    const float* b2       = (const float*)d_in[6];
    const float* fw       = (const float*)d_in[7];
    float* out = (float*)d_out;

    int B = in_sizes[0] / (N_BANDS * TLEN * EMB);

    prep_b2i<<<(N_BANDS * W2ROWS + 255) / 256, 256>>>(b2, fw);
    { dim3 g1(2, 8, N_BANDS);  prep_w1_t<<<g1, 256>>>(W1); }
    { dim3 g2(8, 17, N_BANDS); prep_w2_t<<<g2, 256>>>(W2, fw); }

    cudaFuncSetAttribute(omem_hmma_kernel, cudaFuncAttributeMaxDynamicSharedMemorySize, SMEM_TOTAL);
    dim3 grid(TLEN / TM, N_BANDS, B);
    omem_hmma_kernel<<<grid, NTH, SMEM_TOTAL>>>(q, ln_gamma, ln_beta, b1);

    {
        int total = B * 2 * NFREQ * TLEN;
        gather_kernel<<<(total + 255) / 256, 256>>>(out, B);
    }
}

// round 10
// speedup vs baseline: 10.5313x; 1.2172x over previous
#include <cuda_runtime.h>
#include <cuda_fp16.h>
#include <stdint.h>
#include <math.h>

#define N_BANDS 15
#define BW_     129
#define HOP_    64
#define NFREQ   1025
#define EMB     128
#define MLPD    512
#define TLEN    2048
#define TM      64
#define NTH     256
#define W2ROWS  1032
#define W2PAD   1056
#define NCH2    33

// smem layout (bytes) — 104KB total -> 2 CTAs/SM
#define AH_OFF    0          // h fp16 [64][1024B] swizzled = 65536 (both phases)
#define W1STG_OFF 65536      // GEMM1: 2 x 8192
#define AQN_OFF   81920      // GEMM1: qn [64][256B] = 16384
#define W2STG_OFF 65536      // GEMM2: single 32KB buffer (aliases W1STG+AQN)
#define CMB_OFF   98304      // GEMM2: K-combine, 8KB
#define SMEM_TOTAL 106496

__device__ __align__(16) __half g_W1T[(size_t)N_BANDS * MLPD * EMB];
__device__ __align__(16) __half g_W2T[(size_t)N_BANDS * W2PAD * MLPD];
__device__ float g_b2i[N_BANDS * W2ROWS];
__device__ float g_scr[(size_t)2 * N_BANDS * 516 * TLEN];

__device__ __forceinline__ uint32_t smem_u32(const void* p){
    uint32_t a;
    asm("{ .reg .u64 t; cvta.to.shared.u64 t, %1; cvt.u32.u64 %0, t; }" : "=r"(a) : "l"(p));
    return a;
}
__device__ __forceinline__ void ldsm4(uint32_t* r, uint32_t a){
    asm volatile("ldmatrix.sync.aligned.m8n8.x4.shared.b16 {%0,%1,%2,%3}, [%4];"
        : "=r"(r[0]),"=r"(r[1]),"=r"(r[2]),"=r"(r[3]) : "r"(a));
}
__device__ __forceinline__ void mma16816(float* c, const uint32_t* a, uint32_t b0, uint32_t b1){
    asm volatile("mma.sync.aligned.m16n8k16.row.col.f32.f16.f16.f32 "
        "{%0,%1,%2,%3}, {%4,%5,%6,%7}, {%8,%9}, {%0,%1,%2,%3};"
        : "+f"(c[0]),"+f"(c[1]),"+f"(c[2]),"+f"(c[3])
        : "r"(a[0]),"r"(a[1]),"r"(a[2]),"r"(a[3]),"r"(b0),"r"(b1));
}
__device__ __forceinline__ uint32_t f2h2(float a, float b){
    __half2 h = __floats2half2_rn(a, b);
    return *(uint32_t*)&h;
}
__device__ __forceinline__ void cpa16(uint32_t dst, const void* src){
    asm volatile("cp.async.ca.shared.global [%0], [%1], 16;" :: "r"(dst), "l"(src));
}
__device__ __forceinline__ void cpa_commit(){ asm volatile("cp.async.commit_group;" ::: "memory"); }
__device__ __forceinline__ void cpa_wait0(){ asm volatile("cp.async.wait_group 0;" ::: "memory"); }

__device__ __forceinline__ float tanh_fast(float x){
    x = fminf(fmaxf(x, -15.f), 15.f);
    float e = __expf(2.0f * x);
    return __fdividef(e - 1.0f, e + 1.0f);
}
__device__ __forceinline__ float sigm_fast(float g){
    return __fdividef(1.0f, 1.0f + __expf(-g));
}

// ---------------- prep kernels ----------------
__global__ void prep_b2i(const float* __restrict__ b2, const float* __restrict__ fw){
    int idx = blockIdx.x * blockDim.x + threadIdx.x;
    if (idx >= N_BANDS * W2ROWS) return;
    int r = idx % W2ROWS, n = idx / W2ROWS;
    int j = r >> 1, gbit = r & 1;
    float v = b2[(size_t)n * W2ROWS + (gbit ? j + 516 : j)];
    if (!gbit){
        int cc = j >= 258; int rem = j - cc * 258;
        v *= fw[n * BW_ + (rem >> 1)];
    }
    g_b2i[idx] = v;
}

__global__ void prep_w1_t(const float* __restrict__ W1){
    __shared__ float s[64][65];
    const int n = blockIdx.z, f0 = blockIdx.y * 64, e0 = blockIdx.x * 64;
    const int tid = threadIdx.x;
    const int i0 = tid >> 6, j = tid & 63;
    const float* src = W1 + ((size_t)n * EMB + e0) * MLPD + f0;
    #pragma unroll
    for (int p = 0; p < 16; p++){
        int i = p * 4 + i0;
        s[i][j] = src[(size_t)i * MLPD + j];
    }
    __syncthreads();
    __half* dst = g_W1T + ((size_t)n * MLPD + f0) * EMB + e0;
    #pragma unroll
    for (int p = 0; p < 16; p++){
        int jj = p * 4 + i0;
        dst[(size_t)jj * EMB + j] = __float2half(s[j][jj]);
    }
}

__global__ void prep_w2_t(const float* __restrict__ W2, const float* __restrict__ fw){
    __shared__ float sa[64][33], sg[64][33];
    const int n = blockIdx.z, j0 = blockIdx.y * 32, k0 = blockIdx.x * 64;
    const int tid = threadIdx.x;
    const int kk0 = tid >> 5, jj = tid & 31;
    const float* src = W2 + (size_t)n * MLPD * W2ROWS + (size_t)k0 * W2ROWS;
    const int jf_l = j0 + jj;
    #pragma unroll
    for (int p = 0; p < 8; p++){
        int kk = p * 8 + kk0;
        float va = 0.f, vg = 0.f;
        if (jf_l < 516){
            va = src[(size_t)kk * W2ROWS + jf_l];
            vg = src[(size_t)kk * W2ROWS + 516 + jf_l];
        }
        sa[kk][jj] = va; sg[kk][jj] = vg;
    }
    __syncthreads();
    const int w = tid >> 5, kk2 = tid & 31;
    #pragma unroll
    for (int p = 0; p < 8; p++){
        int rl = p * 8 + w;
        int jj2 = rl >> 1, g = rl & 1;
        int jf = j0 + jj2;
        int r = 2 * jf + g;
        if (r < W2PAD){
            float v0, v1;
            if (g){ v0 = sg[2*kk2][jj2]; v1 = sg[2*kk2+1][jj2]; }
            else {
                v0 = sa[2*kk2][jj2]; v1 = sa[2*kk2+1][jj2];
                if (jf < 516){
                    int cc = jf >= 258; int rem = jf - cc * 258;
                    float fwv = fw[n * BW_ + (rem >> 1)];
                    v0 *= fwv; v1 *= fwv;
                }
            }
            *(__half2*)(g_W2T + ((size_t)n * W2PAD + r) * MLPD + k0 + 2 * kk2) =
                __floats2half2_rn(v0, v1);
        }
    }
}

// ---------------- gather ----------------
__global__ void gather_kernel(float* __restrict__ out, int B){
    int idx = blockIdx.x * blockDim.x + threadIdx.x;
    int total = B * 2 * NFREQ * TLEN;
    if (idx >= total) return;
    int t    = idx & (TLEN - 1);
    int rest = idx >> 11;
    int freq = rest % NFREQ;
    int rest2 = rest / NFREQ;
    int c = rest2 & 1;
    int b = rest2 >> 1;
    int n_lo = (freq >= 128) ? ((freq - 128 + 63) >> 6) : 0;
    int n_hi = freq >> 6; if (n_hi > 14) n_hi = 14;
    float s0 = 0.f, s1 = 0.f;
    for (int n = n_lo; n <= n_hi; n++){
        int f = freq - (n << 6);
        const float* base = g_scr + (((size_t)(b * N_BANDS + n) * 516) + (size_t)(c * 258 + 2 * f)) * TLEN + t;
        s0 += base[0];
        s1 += base[TLEN];
    }
    float2 v; v.x = s0; v.y = s1;
    ((float2*)out)[idx] = v;
}

// ---------------- main kernel ----------------
__global__ __launch_bounds__(NTH, 2)
void omem_hmma_kernel(const float* __restrict__ q,
                      const float* __restrict__ ln_gamma,
                      const float* __restrict__ ln_beta,
                      const float* __restrict__ b1){
    extern __shared__ __align__(1024) char smem[];
    const uint32_t sb = smem_u32(smem);
    const int tid = threadIdx.x, warp = tid >> 5, lane = tid & 31;
    const int wm = warp & 3, whi = warp >> 2;  // GEMM1: N-group; GEMM2: K-half
    const int b = blockIdx.z, n = blockIdx.y, t0 = blockIdx.x * TM;

    // ---- LayerNorm -> qn fp16, swizzled [64][256B] ----
    {
        const float* qb = q + ((size_t)(b * N_BANDS + n) * TLEN + t0) * EMB;
        float4 gg  = ((const float4*)(ln_gamma + (size_t)n * EMB))[lane];
        float4 bet = ((const float4*)(ln_beta  + (size_t)n * EMB))[lane];
        for (int i = warp; i < TM; i += 8){
            float4 v = ((const float4*)(qb + (size_t)i * EMB))[lane];
            float s  = v.x + v.y + v.z + v.w;
            float s2 = v.x*v.x + v.y*v.y + v.z*v.z + v.w*v.w;
            #pragma unroll
            for (int off = 16; off; off >>= 1){
                s  += __shfl_xor_sync(0xffffffffu, s,  off);
                s2 += __shfl_xor_sync(0xffffffffu, s2, off);
            }
            float mu = s * (1.0f/EMB);
            float var = s2 * (1.0f/EMB) - mu*mu;
            float rs = rsqrtf(var + 1e-5f);
            uint2 pk;
            pk.x = f2h2((v.x - mu)*rs*gg.x + bet.x, (v.y - mu)*rs*gg.y + bet.y);
            pk.y = f2h2((v.z - mu)*rs*gg.z + bet.z, (v.w - mu)*rs*gg.w + bet.w);
            uint32_t ch = (uint32_t)(lane >> 1) ^ (uint32_t)(i & 7);
            *(uint2*)(smem + AQN_OFF + i * 256 + ch * 16 + (lane & 1) * 8) = pk;
        }
    }

    const uint32_t aRow = wm * 16 + (lane & 15);
    const uint32_t aS   = aRow & 7;
    const uint32_t aHi  = lane >> 4;
    const uint32_t bRowL = (lane & 7) | ((lane & 16) >> 1);
    const uint32_t bHi   = (lane >> 3) & 1;
    const uint32_t bS    = bRowL & 7;

    uint32_t aOff[4], bOff[4];
    #pragma unroll
    for (int j2 = 0; j2 < 4; j2++){
        aOff[j2] = (((2u*j2 + aHi) ^ aS) << 4);
        bOff[j2] = (((2u*j2 + bHi) ^ bS) << 4);
    }

    __syncthreads();

    // ---- GEMM1: z = qn @ W1T^T (M=64,K=128,N=512), N-split across whi ----
    {
        const __half* W1Tn = g_W1T + (size_t)n * MLPD * EMB;
        const float*  b1n  = b1 + (size_t)n * MLPD;
        uint32_t aA[4];
        #pragma unroll
        for (int j2 = 0; j2 < 4; j2++) aA[j2] = sb + AQN_OFF + aRow * 256 + aOff[j2];
        {
            #pragma unroll
            for (int i = 0; i < 2; i++){
                int lin = i * NTH + tid; int r = lin >> 4, cn = lin & 15;
                cpa16(sb + W1STG_OFF + r * 256 + (((uint32_t)cn ^ (r & 7)) << 4),
                      W1Tn + (size_t)r * EMB + cn * 8);
            }
            cpa_commit();
            cpa_wait0();
        }
        __syncthreads();
        #pragma unroll 1
        for (int c = 0; c < 16; c++){
            const int cbuf = c & 1, nbuf = (c + 1) & 1;
            if (c + 1 < 16){
                #pragma unroll
                for (int i = 0; i < 2; i++){
                    int lin = i * NTH + tid; int r = lin >> 4, cn = lin & 15;
                    cpa16(sb + W1STG_OFF + nbuf * 8192 + r * 256 + (((uint32_t)cn ^ (r & 7)) << 4),
                          W1Tn + (size_t)(c + 1) * 32 * EMB + (size_t)r * EMB + cn * 8);
                }
                cpa_commit();
            }
            float acc[2][4];
            #pragma unroll
            for (int t = 0; t < 2; t++){ acc[t][0]=0.f; acc[t][1]=0.f; acc[t][2]=0.f; acc[t][3]=0.f; }
            uint32_t bA[4];
            #pragma unroll
            for (int j2 = 0; j2 < 4; j2++)
                bA[j2] = sb + W1STG_OFF + cbuf * 8192 + (whi * 16 + bRowL) * 256 + bOff[j2];
            #pragma unroll
            for (int ks = 0; ks < 8; ks++){
                uint32_t a[4], br[4];
                uint32_t ko = (ks >> 2) * 128;
                ldsm4(a,  aA[ks & 3] + ko);
                ldsm4(br, bA[ks & 3] + ko);
                mma16816(acc[0], a, br[0], br[1]);
                mma16816(acc[1], a, br[2], br[3]);
            }
            const uint32_t hr0 = wm * 16 + (lane >> 2);
            const uint32_t hr1 = hr0 + 8;
            #pragma unroll
            for (int t = 0; t < 2; t++){
                int ng = c * 32 + whi * 16 + t * 8 + 2 * (lane & 3);
                float2 bb = *(const float2*)(b1n + ng);
                uint32_t p0 = f2h2(tanh_fast(acc[t][0] + bb.x), tanh_fast(acc[t][1] + bb.y));
                uint32_t p1 = f2h2(tanh_fast(acc[t][2] + bb.x), tanh_fast(acc[t][3] + bb.y));
                uint32_t nbyte = (uint32_t)ng * 2u;
                uint32_t ch = nbyte >> 4, sub = nbyte & 15;
                *(uint32_t*)(smem + AH_OFF + hr0 * 1024 + ((ch ^ (hr0 & 7)) << 4) + sub) = p0;
                *(uint32_t*)(smem + AH_OFF + hr1 * 1024 + ((ch ^ (hr1 & 7)) << 4) + sub) = p1;
            }
            if (c + 1 < 16) cpa_wait0();
            __syncthreads();
        }
    }

    // ---- GEMM2: o = h @ W2T^T (M=64,K=512,Npad=1056), K-split, A cached in regs ----
    {
        const __half* W2Tn = g_W2T + (size_t)n * W2PAD * MLPD;
        const float*  b2in = g_b2i + n * W2ROWS;

        // A-fragment cache: this warp's M=16 x K=256 slice (whi half), loaded ONCE
        uint32_t afr[16][4];
        {
            const uint32_t aB = sb + AH_OFF + aRow * 1024;
            #pragma unroll
            for (int j = 0; j < 16; j++){
                int ks = whi * 16 + j;
                ldsm4(afr[j], aB + aOff[ks & 3] + (uint32_t)(ks >> 2) * 128u);
            }
        }

        // B bases for this K-half (rows 0..15 and 16..31 of each chunk)
        uint32_t bA0[4], bA1[4];
        #pragma unroll
        for (int j2 = 0; j2 < 4; j2++){
            uint32_t base = sb + W2STG_OFF + bRowL * 1024 + bOff[j2] + (uint32_t)whi * 512u;
            bA0[j2] = base;
            bA1[j2] = base + 16 * 1024;
        }

        // preload chunk 0 (32KB)
        {
            #pragma unroll
            for (int i = 0; i < 8; i++){
                int lin = i * NTH + tid; int r = lin >> 6, cn = lin & 63;
                cpa16(sb + W2STG_OFF + r * 1024 + (((uint32_t)cn ^ (r & 7)) << 4),
                      W2Tn + (size_t)r * MLPD + cn * 8);
            }
            cpa_commit();
            cpa_wait0();
        }
        __syncthreads();

        const size_t scrb = (size_t)(b * N_BANDS + n) * 516;
        const int tok0 = t0 + wm * 16 + (lane >> 2);
        const uint32_t cmb = sb + CMB_OFF + (uint32_t)wm * 2048u + (uint32_t)lane * 16u;

        #pragma unroll 1
        for (int c = 0; c < NCH2; c++){
            float acc[4][4];
            #pragma unroll
            for (int t = 0; t < 4; t++){ acc[t][0]=0.f; acc[t][1]=0.f; acc[t][2]=0.f; acc[t][3]=0.f; }
            #pragma unroll
            for (int j = 0; j < 16; j++){
                uint32_t ko = (uint32_t)(j >> 2) * 128u;
                uint32_t br0[4], br1[4];
                ldsm4(br0, bA0[j & 3] + ko);
                ldsm4(br1, bA1[j & 3] + ko);
                mma16816(acc[0], afr[j], br0[0], br0[1]);
                mma16816(acc[1], afr[j], br0[2], br0[3]);
                mma16816(acc[2], afr[j], br1[0], br1[1]);
                mma16816(acc[3], afr[j], br1[2], br1[3]);
            }
            // khalf 1 publishes partials
            if (whi){
                #pragma unroll
                for (int t = 0; t < 4; t++){
                    float4 v; v.x = acc[t][0]; v.y = acc[t][1]; v.z = acc[t][2]; v.w = acc[t][3];
                    *(float4*)(smem + (cmb - sb) + t * 512) = v;
                }
            }
            __syncthreads();   // partials visible; chunk buffer free for reload
            if (c + 1 < NCH2){
                const __half* src = W2Tn + (size_t)(c + 1) * 32 * MLPD;
                #pragma unroll
                for (int i = 0; i < 8; i++){
                    int lin = i * NTH + tid; int r = lin >> 6, cn = lin & 63;
                    cpa16(sb + W2STG_OFF + r * 1024 + (((uint32_t)cn ^ (r & 7)) << 4),
                          src + (size_t)r * MLPD + cn * 8);
                }
                cpa_commit();
            }
            // khalf 0 combines + epilogue (overlaps the async load)
            if (!whi){
                #pragma unroll
                for (int t = 0; t < 4; t++){
                    float4 v = *(const float4*)(smem + (cmb - sb) + t * 512);
                    int jp = c * 16 + t * 4 + (lane & 3);
                    if (jp < 516){
                        float2 bb = *(const float2*)(b2in + 2 * jp);
                        float a0 = acc[t][0] + v.x + bb.x, g0 = acc[t][1] + v.y + bb.y;
                        float a1 = acc[t][2] + v.z + bb.x, g1 = acc[t][3] + v.w + bb.y;
                        float* dst = g_scr + (scrb + (size_t)jp) * TLEN + tok0;
                        dst[0] = a0 * sigm_fast(g0);
                        dst[8] = a1 * sigm_fast(g1);
                    }
                }
            }
            if (c + 1 < NCH2) cpa_wait0();
            __syncthreads();
        }
    }
}

extern "C" void kernel_launch(void* const* d_in, const int* in_sizes, int n_in,
                              void* d_out, int out_size){
    const float* q        = (const float*)d_in[0];
    const float* ln_gamma = (const float*)d_in[1];
    const float* ln_beta  = (const float*)d_in[2];
    const float* W1       = (const float*)d_in[3];
    const float* b1       = (const float*)d_in[4];
    const float* W2       = (const float*)d_in[5];
    const float* b2       = (const float*)d_in[6];
    const float* fw       = (const float*)d_in[7];
    float* out = (float*)d_out;

    int B = in_sizes[0] / (N_BANDS * TLEN * EMB);

    prep_b2i<<<(N_BANDS * W2ROWS + 255) / 256, 256>>>(b2, fw);
    { dim3 g1(2, 8, N_BANDS);  prep_w1_t<<<g1, 256>>>(W1); }
    { dim3 g2(8, 17, N_BANDS); prep_w2_t<<<g2, 256>>>(W2, fw); }

    cudaFuncSetAttribute(omem_hmma_kernel, cudaFuncAttributeMaxDynamicSharedMemorySize, SMEM_TOTAL);
    dim3 grid(TLEN / TM, N_BANDS, B);
    omem_hmma_kernel<<<grid, NTH, SMEM_TOTAL>>>(q, ln_gamma, ln_beta, b1);

    {
        int total = B * 2 * NFREQ * TLEN;
        gather_kernel<<<(total + 255) / 256, 256>>>(out, B);
    }
}